// round 15
// baseline (speedup 1.0000x reference)
#include <cuda_runtime.h>
#include <cuda_bf16.h>
#include <math.h>
#include <stdint.h>

// Problem constants
#define BQ   16384          // B*S rows
#define HIDC 2048
#define NH   16
#define DD   128
#define NBANK 4
#define EPSF 1e-6f
#define GK   2048
#define QKVW 6144           // fused qkv row width

#define OUT_MEM  ((size_t)BQ * HIDC)
#define OUT_NORM (OUT_MEM + (size_t)NH * DD * DD)

// -------- scratch (static device globals; no runtime allocation) ----------
__device__ float g_qkv[(size_t)BQ * QKVW];            // fused q|k|v projections
__device__ float g_part[(size_t)NH * 64 * DD * DD];   // mem-update partials (64 slices)
__device__ float g_nsum[(size_t)NH * 128 * DD];
__device__ float g_weff[NH][NBANK];

// bf16 hi/lo split buffers
__device__ __nv_bfloat16 g_hs_hi[(size_t)BQ * HIDC];
__device__ __nv_bfloat16 g_hs_lo[(size_t)BQ * HIDC];
__device__ __nv_bfloat16 g_w_hi[4][(size_t)HIDC * HIDC];   // Wq,Wk,Wv,Wo (contiguous)
__device__ __nv_bfloat16 g_w_lo[4][(size_t)HIDC * HIDC];
__device__ __nv_bfloat16 g_cb_hi[(size_t)BQ * HIDC];       // combined hi/lo
__device__ __nv_bfloat16 g_cb_lo[(size_t)BQ * HIDC];

// pre-swizzled transposed memories (B-operand layout) + norm tiles
__device__ __nv_bfloat16 g_mTh[(size_t)NBANK * NH * DD * DD];
__device__ __nv_bfloat16 g_mTl[(size_t)NBANK * NH * DD * DD];
__device__ __nv_bfloat16 g_nTh[(size_t)NH * 1024];
__device__ __nv_bfloat16 g_nTl[(size_t)NH * 1024];

__device__ __forceinline__ float sigf(float x) { return x > 0.f ? x + 1.f : expf(x); }

__device__ __forceinline__ uint32_t smem_to_u32(const void* p) {
    uint32_t a;
    asm("{ .reg .u64 t; cvta.to.shared.u64 t, %1; cvt.u32.u64 %0, t; }" : "=r"(a) : "l"(p));
    return a;
}
#define SW128(off) ((off) ^ (((off) >> 3) & 0x70))

__device__ __forceinline__ void cp_async16(uint32_t saddr, const void* gaddr) {
    asm volatile("cp.async.cg.shared.global [%0], [%1], 16;" :: "r"(saddr), "l"(gaddr));
}
__device__ __forceinline__ void cp_commit() {
    asm volatile("cp.async.commit_group;" ::: "memory");
}
__device__ __forceinline__ void ldsm4(uint32_t* r, uint32_t addr) {
    asm volatile("ldmatrix.sync.aligned.m8n8.x4.shared.b16 {%0,%1,%2,%3}, [%4];"
        : "=r"(r[0]), "=r"(r[1]), "=r"(r[2]), "=r"(r[3]) : "r"(addr));
}
__device__ __forceinline__ void ldsm4t(uint32_t* r, uint32_t addr) {
    asm volatile("ldmatrix.sync.aligned.m8n8.x4.trans.shared.b16 {%0,%1,%2,%3}, [%4];"
        : "=r"(r[0]), "=r"(r[1]), "=r"(r[2]), "=r"(r[3]) : "r"(addr));
}
__device__ __forceinline__ void ldsm2(uint32_t* r, uint32_t addr) {
    asm volatile("ldmatrix.sync.aligned.m8n8.x2.shared.b16 {%0,%1}, [%2];"
        : "=r"(r[0]), "=r"(r[1]) : "r"(addr));
}
__device__ __forceinline__ void mma_bf16(float* c, const uint32_t* a, const uint32_t* b) {
    asm volatile("mma.sync.aligned.m16n8k16.row.col.f32.bf16.bf16.f32 "
        "{%0,%1,%2,%3}, {%4,%5,%6,%7}, {%8,%9}, {%0,%1,%2,%3};"
        : "+f"(c[0]), "+f"(c[1]), "+f"(c[2]), "+f"(c[3])
        : "r"(a[0]), "r"(a[1]), "r"(a[2]), "r"(a[3]), "r"(b[0]), "r"(b[1]));
}

// ===================== fp32 -> bf16 hi/lo split =====================
__global__ void cvt_split_kernel(const float* __restrict__ x,
                                 __nv_bfloat16* __restrict__ hi,
                                 __nv_bfloat16* __restrict__ lo)
{
    size_t i = ((size_t)blockIdx.x * blockDim.x + threadIdx.x) * 4;
    float4 v = *(const float4*)(x + i);
    __nv_bfloat16 h0 = __float2bfloat16(v.x), h1 = __float2bfloat16(v.y);
    __nv_bfloat16 h2 = __float2bfloat16(v.z), h3 = __float2bfloat16(v.w);
    __nv_bfloat16 l0 = __float2bfloat16(v.x - __bfloat162float(h0));
    __nv_bfloat16 l1 = __float2bfloat16(v.y - __bfloat162float(h1));
    __nv_bfloat16 l2 = __float2bfloat16(v.z - __bfloat162float(h2));
    __nv_bfloat16 l3 = __float2bfloat16(v.w - __bfloat162float(h3));
    __nv_bfloat162* ph = (__nv_bfloat162*)(hi + i);
    __nv_bfloat162* pl = (__nv_bfloat162*)(lo + i);
    ph[0] = __nv_bfloat162(h0, h1); ph[1] = __nv_bfloat162(h2, h3);
    pl[0] = __nv_bfloat162(l0, l1); pl[1] = __nv_bfloat162(l2, l3);
}

// ===================== HMMA GEMM: C[M,N] = A[M,K] @ B[N,K]^T =====================
// bf16 hi/lo 3-pass. Block 128(m) x 256(n), warp tile 64x64, K-chunk 64, 2-stage.
#define SA_H 0
#define SA_L 16384
#define SB_H 32768
#define SB_L 65536
#define STG2 98304
#define NCHUNK 32           // K / 64
#define HG_SMEM (2 * STG2 + 1024)

__device__ __forceinline__ void load_stage(
    const __nv_bfloat16* __restrict__ Ah, const __nv_bfloat16* __restrict__ Al,
    const __nv_bfloat16* __restrict__ Bh, const __nv_bfloat16* __restrict__ Bl,
    uint32_t sb, int bm, int bn, int k0, int tid)
{
    #pragma unroll
    for (int it = 0; it < 4; it++) {
        int id = tid + it * 256;            // 0..1023 : A rows 0..127
        int r = id >> 3, c = id & 7;
        uint32_t sw = SW128((uint32_t)(r * 128 + c * 16));
        size_t ga = (size_t)(bm + r) * GK + k0 + c * 8;
        cp_async16(sb + SA_H + sw, Ah + ga);
        cp_async16(sb + SA_L + sw, Al + ga);
    }
    #pragma unroll
    for (int it = 0; it < 8; it++) {
        int id = tid + it * 256;            // 0..2047 : B rows 0..255
        int r = id >> 3, c = id & 7;
        uint32_t sw = SW128((uint32_t)(r * 128 + c * 16));
        size_t gb = (size_t)(bn + r) * GK + k0 + c * 8;
        cp_async16(sb + SB_H + sw, Bh + gb);
        cp_async16(sb + SB_L + sw, Bl + gb);
    }
}

__global__ __launch_bounds__(256, 1)
void hgemm_kernel(const __nv_bfloat16* __restrict__ Ah, const __nv_bfloat16* __restrict__ Al,
                  const __nv_bfloat16* __restrict__ Bh, const __nv_bfloat16* __restrict__ Bl,
                  float* __restrict__ C, int N)
{
    extern __shared__ char smem[];
    uint32_t sraw = smem_to_u32(smem);
    uint32_t sal = (sraw + 1023u) & ~1023u;

    int tid = threadIdx.x;
    int lane = tid & 31, wid = tid >> 5;
    int wm = wid >> 2, wn = wid & 3;        // warp tile 64(m) x 64(n), 2x4 warps
    int bm = blockIdx.y * 128;
    int bn = blockIdx.x * 256;

    float acc[4][8][4];
    #pragma unroll
    for (int t = 0; t < 4; t++)
        #pragma unroll
        for (int n = 0; n < 8; n++)
            #pragma unroll
            for (int j = 0; j < 4; j++) acc[t][n][j] = 0.f;

    load_stage(Ah, Al, Bh, Bl, sal, bm, bn, 0, tid);
    cp_commit();
    load_stage(Ah, Al, Bh, Bl, sal + STG2, bm, bn, 64, tid);
    cp_commit();

    uint32_t a_base = (uint32_t)((wm * 64 + (lane & 15)) * 128 + (lane >> 4) * 16);
    uint32_t b_base = (uint32_t)((wn * 64 + ((lane >> 4) << 3) + (lane & 7)) * 128 +
                                 ((lane >> 3) & 1) * 16);

    for (int c = 0; c < NCHUNK; c++) {
        if (c == NCHUNK - 1) { asm volatile("cp.async.wait_group 0;" ::: "memory"); }
        else                 { asm volatile("cp.async.wait_group 1;" ::: "memory"); }
        __syncthreads();
        uint32_t sb = sal + (c & 1) * STG2;

        #pragma unroll
        for (int ks = 0; ks < 4; ks++) {
            uint32_t ah[4][4], al[4][4];
            #pragma unroll
            for (int t = 0; t < 4; t++) {
                uint32_t aaddr = sb + SA_H + SW128(a_base + t * 16 * 128 + ks * 32);
                ldsm4(ah[t], aaddr);
                ldsm4(al[t], aaddr + (SA_L - SA_H));
            }
            #pragma unroll
            for (int ng = 0; ng < 4; ng++) {
                uint32_t baddr = sb + SB_H + SW128(b_base + ng * 16 * 128 + ks * 32);
                uint32_t bh[4], bl[4];
                ldsm4(bh, baddr);
                ldsm4(bl, baddr + (SB_L - SB_H));
                // pass-outer / t-inner order: dependent MMAs on the same acc are 8 apart
                #pragma unroll
                for (int t = 0; t < 4; t++) mma_bf16(acc[t][ng * 2 + 0], ah[t], bh);
                #pragma unroll
                for (int t = 0; t < 4; t++) mma_bf16(acc[t][ng * 2 + 1], ah[t], bh + 2);
                #pragma unroll
                for (int t = 0; t < 4; t++) mma_bf16(acc[t][ng * 2 + 0], ah[t], bl);
                #pragma unroll
                for (int t = 0; t < 4; t++) mma_bf16(acc[t][ng * 2 + 1], ah[t], bl + 2);
                #pragma unroll
                for (int t = 0; t < 4; t++) mma_bf16(acc[t][ng * 2 + 0], al[t], bh);
                #pragma unroll
                for (int t = 0; t < 4; t++) mma_bf16(acc[t][ng * 2 + 1], al[t], bh + 2);
            }
        }
        __syncthreads();
        if (c + 2 < NCHUNK) {
            load_stage(Ah, Al, Bh, Bl, sal + (c & 1) * STG2, bm, bn, (c + 2) * 64, tid);
            cp_commit();
        }
    }

    #pragma unroll
    for (int t = 0; t < 4; t++) {
        int r0 = bm + wm * 64 + t * 16 + (lane >> 2);
        #pragma unroll
        for (int nt = 0; nt < 8; nt++) {
            int col = bn + wn * 64 + nt * 8 + (lane & 3) * 2;
            *(float2*)&C[(size_t)r0 * N + col]       = make_float2(acc[t][nt][0], acc[t][nt][1]);
            *(float2*)&C[(size_t)(r0 + 8) * N + col] = make_float2(acc[t][nt][2], acc[t][nt][3]);
        }
    }
}

// ===================== K0: softmax of bank weights + active flags =====================
__global__ void prep_kernel(const float* __restrict__ bw, const float* __restrict__ mn) {
    __shared__ float bsum[NBANK];
    int tid = threadIdx.x;
    int w = tid >> 5, lane = tid & 31;
    if (w < NBANK) {
        float s = 0.f;
        for (int i = lane; i < NH * DD; i += 32) s += mn[w * NH * DD + i];
        #pragma unroll
        for (int o = 16; o; o >>= 1) s += __shfl_down_sync(0xffffffffu, s, o);
        if (lane == 0) bsum[w] = s;
    }
    __syncthreads();
    if (tid < NH) {
        float x0 = bw[tid * 4 + 0], x1 = bw[tid * 4 + 1];
        float x2 = bw[tid * 4 + 2], x3 = bw[tid * 4 + 3];
        float m = fmaxf(fmaxf(x0, x1), fmaxf(x2, x3));
        float e0 = expf(x0 - m), e1 = expf(x1 - m), e2 = expf(x2 - m), e3 = expf(x3 - m);
        float inv = 1.f / (e0 + e1 + e2 + e3);
        g_weff[tid][0] = e0 * inv * (bsum[0] >= EPSF ? 1.f : 0.f);
        g_weff[tid][1] = e1 * inv * (bsum[1] >= EPSF ? 1.f : 0.f);
        g_weff[tid][2] = e2 * inv * (bsum[2] >= EPSF ? 1.f : 0.f);
        g_weff[tid][3] = e3 * inv * (bsum[3] >= EPSF ? 1.f : 0.f);
    }
}

// ===================== prep2: memories -> transposed, split, pre-swizzled =====================
__global__ void prep2_kernel(const float* __restrict__ mem,
                             __nv_bfloat16* __restrict__ mTh, __nv_bfloat16* __restrict__ mTl)
{
    int nh = blockIdx.x;     // 0..63
    const float* src = mem + (size_t)nh * 16384;
    __nv_bfloat16* dh = mTh + (size_t)nh * 16384;
    __nv_bfloat16* dl = mTl + (size_t)nh * 16384;
    for (int i = threadIdx.x; i < 16384; i += 256) {
        int d = i >> 7, e = i & 127;
        float v = src[d * 128 + e];
        __nv_bfloat16 hi = __float2bfloat16(v);
        __nv_bfloat16 lo = __float2bfloat16(v - __bfloat162float(hi));
        uint32_t off = ((uint32_t)(d >> 6) << 13) +
                       (SW128((uint32_t)(e * 128 + (d & 63) * 2)) >> 1);
        dh[off] = hi; dl[off] = lo;
    }
}

__global__ void normt_kernel(const float* __restrict__ mnm,
                             __nv_bfloat16* __restrict__ nTh, __nv_bfloat16* __restrict__ nTl)
{
    int h = blockIdx.x;
    for (int i = threadIdx.x; i < 1024; i += 256) {
        int nr = i >> 7, d = i & 127;
        float v = (nr < NBANK) ? mnm[(size_t)(nr * NH + h) * DD + d] : 0.f;
        __nv_bfloat16 hi = __float2bfloat16(v);
        __nv_bfloat16 lo = __float2bfloat16(v - __bfloat162float(hi));
        uint32_t off = ((uint32_t)(d >> 6) << 9) +
                       (SW128((uint32_t)(nr * 128 + (d & 63) * 2)) >> 1);
        nTh[h * 1024 + off] = hi; nTl[h * 1024 + off] = lo;
    }
}

// ===================== HMMA combined / deltav =====================
#define CB_SAH   0
#define CB_SAL   32768
#define CB_SB    65536
#define CB_SNTH  196608
#define CB_SNTL  198656
#define CB_SNORM 200704
#define CB_SCOEF 202752
#define CB_SSUM  204800
#define CB_SMEM  207872

__device__ __forceinline__ void sigma_to_smem(const float* __restrict__ src, int row0,
                                              int colbase, int stride, char* sb, int tid)
{
    #pragma unroll
    for (int i = 0; i < 16; i++) {
        int id = tid + i * 256;
        int r = id >> 5, c4 = id & 31;
        float4 v = *(const float4*)&src[(size_t)(row0 + r) * stride + colbase + c4 * 4];
        float s0 = sigf(v.x), s1 = sigf(v.y), s2 = sigf(v.z), s3 = sigf(v.w);
        __nv_bfloat16 h0 = __float2bfloat16(s0), h1 = __float2bfloat16(s1);
        __nv_bfloat16 h2 = __float2bfloat16(s2), h3 = __float2bfloat16(s3);
        __nv_bfloat16 l0 = __float2bfloat16(s0 - __bfloat162float(h0));
        __nv_bfloat16 l1 = __float2bfloat16(s1 - __bfloat162float(h1));
        __nv_bfloat16 l2 = __float2bfloat16(s2 - __bfloat162float(h2));
        __nv_bfloat16 l3 = __float2bfloat16(s3 - __bfloat162float(h3));
        int d0 = c4 * 4;
        uint32_t off = (uint32_t)((d0 >> 6) * 16384) + SW128((uint32_t)(r * 128 + (d0 & 63) * 2));
        *(__nv_bfloat162*)(sb + CB_SAH + off)     = __nv_bfloat162(h0, h1);
        *(__nv_bfloat162*)(sb + CB_SAH + off + 4) = __nv_bfloat162(h2, h3);
        *(__nv_bfloat162*)(sb + CB_SAL + off)     = __nv_bfloat162(l0, l1);
        *(__nv_bfloat162*)(sb + CB_SAL + off + 4) = __nv_bfloat162(l2, l3);
    }
}

__device__ __forceinline__ void norm_mma(uint32_t sal, char* sb, int wm, int lane)
{
    float nc[2][4];
    #pragma unroll
    for (int t = 0; t < 2; t++)
        #pragma unroll
        for (int j = 0; j < 4; j++) nc[t][j] = 0.f;
    #pragma unroll
    for (int ks = 0; ks < 8; ks++) {
        uint32_t ah[2][4], al[2][4];
        #pragma unroll
        for (int t = 0; t < 2; t++) {
            uint32_t aaddr = sal + CB_SAH + (ks >> 2) * 16384 +
                SW128((uint32_t)((wm * 32 + t * 16 + (lane & 15)) * 128 + (ks & 3) * 32 + (lane >> 4) * 16));
            ldsm4(ah[t], aaddr);
            ldsm4(al[t], aaddr + 32768);
        }
        uint32_t bh[2], bl[2];
        uint32_t naddr = sal + CB_SNTH + (ks >> 2) * 1024 +
            SW128((uint32_t)((lane & 7) * 128 + (ks & 3) * 32 + ((lane >> 3) & 1) * 16));
        ldsm2(bh, naddr);
        ldsm2(bl, naddr + 2048);
        #pragma unroll
        for (int t = 0; t < 2; t++) mma_bf16(nc[t], ah[t], bh);
        #pragma unroll
        for (int t = 0; t < 2; t++) mma_bf16(nc[t], al[t], bh);
        #pragma unroll
        for (int t = 0; t < 2; t++) mma_bf16(nc[t], ah[t], bl);
    }
    float* sN = (float*)(sb + CB_SNORM);
    if ((lane & 3) < 2) {
        #pragma unroll
        for (int t = 0; t < 2; t++) {
            int rr = wm * 32 + t * 16 + (lane >> 2);
            sN[rr * 4 + (lane & 3) * 2]           = nc[t][0];
            sN[rr * 4 + (lane & 3) * 2 + 1]       = nc[t][1];
            sN[(rr + 8) * 4 + (lane & 3) * 2]     = nc[t][2];
            sN[(rr + 8) * 4 + (lane & 3) * 2 + 1] = nc[t][3];
        }
    }
}

__device__ __forceinline__ void bank_mma(uint32_t sal, uint32_t sbB, int wm, int wn, int lane,
                                         float acc[2][8][4])
{
    #pragma unroll
    for (int ks = 0; ks < 8; ks++) {
        uint32_t ah[2][4], al[2][4];
        #pragma unroll
        for (int t = 0; t < 2; t++) {
            uint32_t aaddr = sal + CB_SAH + (ks >> 2) * 16384 +
                SW128((uint32_t)((wm * 32 + t * 16 + (lane & 15)) * 128 + (ks & 3) * 32 + (lane >> 4) * 16));
            ldsm4(ah[t], aaddr);
            ldsm4(al[t], aaddr + 32768);
        }
        #pragma unroll
        for (int nt = 0; nt < 4; nt++) {
            uint32_t baddr = sbB + (ks >> 2) * 16384 +
                SW128((uint32_t)((wn * 64 + nt * 16 + ((lane >> 4) << 3) + (lane & 7)) * 128 +
                                 (ks & 3) * 32 + ((lane >> 3) & 1) * 16));
            uint32_t bh[4], bl[4];
            ldsm4(bh, baddr);
            ldsm4(bl, baddr + 32768);
            #pragma unroll
            for (int t = 0; t < 2; t++) mma_bf16(acc[t][nt * 2 + 0], ah[t], bh);
            #pragma unroll
            for (int t = 0; t < 2; t++) mma_bf16(acc[t][nt * 2 + 1], ah[t], bh + 2);
            #pragma unroll
            for (int t = 0; t < 2; t++) mma_bf16(acc[t][nt * 2 + 0], ah[t], bl);
            #pragma unroll
            for (int t = 0; t < 2; t++) mma_bf16(acc[t][nt * 2 + 1], ah[t], bl + 2);
            #pragma unroll
            for (int t = 0; t < 2; t++) mma_bf16(acc[t][nt * 2 + 0], al[t], bh);
            #pragma unroll
            for (int t = 0; t < 2; t++) mma_bf16(acc[t][nt * 2 + 1], al[t], bh + 2);
        }
    }
}

__device__ __forceinline__ void copy_bank(const __nv_bfloat16* mTh, const __nv_bfloat16* mTl,
                                          int n, int h, int buf, uint32_t sal, int tid)
{
    const __nv_bfloat16* sh = mTh + ((size_t)(n * NH + h) << 14);
    const __nv_bfloat16* sl = mTl + ((size_t)(n * NH + h) << 14);
    uint32_t dst = sal + CB_SB + buf * 65536;
    #pragma unroll
    for (int i = 0; i < 8; i++) {
        int id = tid + i * 256;
        cp_async16(dst + id * 16, sh + id * 8);
        cp_async16(dst + 32768 + id * 16, sl + id * 8);
    }
}

__global__ __launch_bounds__(256, 1) void combined_hmma(
    const float* __restrict__ qkv,
    const __nv_bfloat16* __restrict__ mTh, const __nv_bfloat16* __restrict__ mTl,
    const __nv_bfloat16* __restrict__ nTh, const __nv_bfloat16* __restrict__ nTl,
    __nv_bfloat16* __restrict__ cbh, __nv_bfloat16* __restrict__ cbl)
{
    extern __shared__ char smem[];
    uint32_t sraw = smem_to_u32(smem);
    uint32_t sal = (sraw + 1023u) & ~1023u;
    char* sb = smem + (sal - sraw);
    int tid = threadIdx.x, lane = tid & 31, wid = tid >> 5;
    int wm = wid & 3, wn = wid >> 2;
    int h = blockIdx.y;
    int row0 = blockIdx.x * 128;

    copy_bank(mTh, mTl, 0, h, 0, sal, tid);
    if (tid < 128) {
        cp_async16(sal + CB_SNTH + tid * 16, nTh + h * 1024 + tid * 8);
        cp_async16(sal + CB_SNTL + tid * 16, nTl + h * 1024 + tid * 8);
    }
    cp_commit();
    copy_bank(mTh, mTl, 1, h, 1, sal, tid);
    cp_commit();

    sigma_to_smem(qkv, row0, h * DD, QKVW, sb, tid);   // q columns
    __syncthreads();

    asm volatile("cp.async.wait_group 1;" ::: "memory");
    __syncthreads();
    if (wn == 0) norm_mma(sal, sb, wm, lane);
    __syncthreads();

    float* sN = (float*)(sb + CB_SNORM);
    float* sC = (float*)(sb + CB_SCOEF);
    {
        int rr = tid >> 1, base = (tid & 1) * 2;
        sC[rr * 4 + base]     = g_weff[h][base]     / fmaxf(sN[rr * 4 + base], EPSF);
        sC[rr * 4 + base + 1] = g_weff[h][base + 1] / fmaxf(sN[rr * 4 + base + 1], EPSF);
    }
    __syncthreads();

    float fin[2][8][4];
    #pragma unroll
    for (int t = 0; t < 2; t++)
        #pragma unroll
        for (int j = 0; j < 8; j++)
            #pragma unroll
            for (int p = 0; p < 4; p++) fin[t][j][p] = 0.f;

    for (int n = 0; n < NBANK; n++) {
        if (n < 3) { asm volatile("cp.async.wait_group 1;" ::: "memory"); }
        else       { asm volatile("cp.async.wait_group 0;" ::: "memory"); }
        __syncthreads();
        float acc[2][8][4];
        #pragma unroll
        for (int t = 0; t < 2; t++)
            #pragma unroll
            for (int j = 0; j < 8; j++)
                #pragma unroll
                for (int p = 0; p < 4; p++) acc[t][j][p] = 0.f;
        bank_mma(sal, sal + CB_SB + (n & 1) * 65536, wm, wn, lane, acc);
        __syncthreads();
        if (n + 2 < NBANK) { copy_bank(mTh, mTl, n + 2, h, n & 1, sal, tid); cp_commit(); }
        #pragma unroll
        for (int t = 0; t < 2; t++) {
            int rrA = wm * 32 + t * 16 + (lane >> 2);
            float cA = sC[rrA * 4 + n], cB = sC[(rrA + 8) * 4 + n];
            #pragma unroll
            for (int j = 0; j < 8; j++) {
                fin[t][j][0] += cA * acc[t][j][0];
                fin[t][j][1] += cA * acc[t][j][1];
                fin[t][j][2] += cB * acc[t][j][2];
                fin[t][j][3] += cB * acc[t][j][3];
            }
        }
    }

    #pragma unroll
    for (int t = 0; t < 2; t++) {
        int rr = row0 + wm * 32 + t * 16 + (lane >> 2);
        #pragma unroll
        for (int j = 0; j < 8; j++) {
            int col = h * DD + wn * 64 + j * 8 + (lane & 3) * 2;
            #pragma unroll
            for (int half = 0; half < 2; half++) {
                float f0 = fin[t][j][half * 2 + 0], f1 = fin[t][j][half * 2 + 1];
                __nv_bfloat16 h0 = __float2bfloat16(f0), h1 = __float2bfloat16(f1);
                __nv_bfloat16 l0 = __float2bfloat16(f0 - __bfloat162float(h0));
                __nv_bfloat16 l1 = __float2bfloat16(f1 - __bfloat162float(h1));
                size_t off = (size_t)(rr + half * 8) * HIDC + col;
                *(__nv_bfloat162*)(cbh + off) = __nv_bfloat162(h0, h1);
                *(__nv_bfloat162*)(cbl + off) = __nv_bfloat162(l0, l1);
            }
        }
    }
}

// deltav + fused mem-update: 2 sub-tiles (256 rows) per block, bank0 copied once,
// P accumulated across sub-tiles -> g_part has 64 slices per head.
__global__ __launch_bounds__(256, 1) void deltav_hmma(
    const float* __restrict__ qkv,
    const __nv_bfloat16* __restrict__ mTh, const __nv_bfloat16* __restrict__ mTl,
    const __nv_bfloat16* __restrict__ nTh, const __nv_bfloat16* __restrict__ nTl,
    float* __restrict__ nsum, float* __restrict__ part)
{
    extern __shared__ char smem[];
    uint32_t sraw = smem_to_u32(smem);
    uint32_t sal = (sraw + 1023u) & ~1023u;
    char* sb = smem + (sal - sraw);
    int tid = threadIdx.x, lane = tid & 31, wid = tid >> 5;
    int wm = wid & 3, wn = wid >> 2;
    int h = blockIdx.y;
    int bx = blockIdx.x;            // 0..63

    copy_bank(mTh, mTl, 0, h, 0, sal, tid);
    if (tid < 128) {
        cp_async16(sal + CB_SNTH + tid * 16, nTh + h * 1024 + tid * 8);
        cp_async16(sal + CB_SNTL + tid * 16, nTl + h * 1024 + tid * 8);
    }
    cp_commit();

    float pac[2][8][4];
    #pragma unroll
    for (int t = 0; t < 2; t++)
        #pragma unroll
        for (int j = 0; j < 8; j++)
            #pragma unroll
            for (int p = 0; p < 4; p++) pac[t][j][p] = 0.f;

    const uint32_t DVB = CB_SB + 65536;   // dv hi/lo buffer (bank buf1 slot)

    for (int st = 0; st < 2; st++) {
        int row0 = bx * 256 + st * 128;
        if (st) __syncthreads();          // P-mma of st=0 done reading sA/dv

        sigma_to_smem(qkv, row0, 2048 + h * DD, QKVW, sb, tid);   // k columns
        __syncthreads();
        if (st == 0) {
            asm volatile("cp.async.wait_group 0;" ::: "memory");
            __syncthreads();
        }
        if (wn == 0) norm_mma(sal, sb, wm, lane);

        {   // column sums of sigma_k (hi+lo) over this 128-row tile
            int col = tid & 127, hf = tid >> 7;
            float s = 0.f;
            for (int r = hf * 64; r < hf * 64 + 64; r++) {
                uint32_t off = (uint32_t)((col >> 6) * 16384) + SW128((uint32_t)(r * 128 + (col & 63) * 2));
                s += __bfloat162float(*(__nv_bfloat16*)(sb + CB_SAH + off))
                   + __bfloat162float(*(__nv_bfloat16*)(sb + CB_SAL + off));
            }
            ((float*)(sb + CB_SSUM))[hf * 128 + col] = s;
        }
        __syncthreads();

        float* sN = (float*)(sb + CB_SNORM);
        float* sC = (float*)(sb + CB_SCOEF);
        if (tid < 128) {
            sC[tid] = 1.f / fmaxf(sN[tid * 4], EPSF);
            float* ss = (float*)(sb + CB_SSUM);
            nsum[(size_t)(h * 128 + bx * 2 + st) * DD + tid] = ss[tid] + ss[128 + tid];
        }
        __syncthreads();

        float acc[2][8][4];
        #pragma unroll
        for (int t = 0; t < 2; t++)
            #pragma unroll
            for (int j = 0; j < 8; j++)
                #pragma unroll
                for (int p = 0; p < 4; p++) acc[t][j][p] = 0.f;
        bank_mma(sal, sal + CB_SB, wm, wn, lane, acc);

        // dv = v - acc*inv -> smem bf16 hi/lo at DVB (does not touch bank0)
        #pragma unroll
        for (int t = 0; t < 2; t++) {
            int rloc = wm * 32 + t * 16 + (lane >> 2);
            float invA = sC[rloc], invB = sC[rloc + 8];
            int rr = row0 + rloc;
            #pragma unroll
            for (int j = 0; j < 8; j++) {
                int eloc = wn * 64 + j * 8 + (lane & 3) * 2;
                int col = 4096 + h * DD + eloc;     // v columns
                float2 v0 = *(const float2*)&qkv[(size_t)rr * QKVW + col];
                float2 v1 = *(const float2*)&qkv[(size_t)(rr + 8) * QKVW + col];
                float d00 = v0.x - acc[t][j][0] * invA, d01 = v0.y - acc[t][j][1] * invA;
                float d10 = v1.x - acc[t][j][2] * invB, d11 = v1.y - acc[t][j][3] * invB;
                uint32_t off0 = ((uint32_t)(eloc >> 6) << 14) + SW128((uint32_t)(rloc * 128 + (eloc & 63) * 2));
                uint32_t off1 = ((uint32_t)(eloc >> 6) << 14) + SW128((uint32_t)((rloc + 8) * 128 + (eloc & 63) * 2));
                __nv_bfloat16 h00 = __float2bfloat16(d00), h01 = __float2bfloat16(d01);
                __nv_bfloat16 h10 = __float2bfloat16(d10), h11 = __float2bfloat16(d11);
                *(__nv_bfloat162*)(sb + DVB + off0) = __nv_bfloat162(h00, h01);
                *(__nv_bfloat162*)(sb + DVB + off1) = __nv_bfloat162(h10, h11);
                *(__nv_bfloat162*)(sb + DVB + 32768 + off0) =
                    __nv_bfloat162(__float2bfloat16(d00 - __bfloat162float(h00)),
                                   __float2bfloat16(d01 - __bfloat162float(h01)));
                *(__nv_bfloat162*)(sb + DVB + 32768 + off1) =
                    __nv_bfloat162(__float2bfloat16(d10 - __bfloat162float(h10)),
                                   __float2bfloat16(d11 - __bfloat162float(h11)));
            }
        }
        __syncthreads();

        // P += sk^T @ dv  (both k(=r)-major in smem -> ldmatrix.trans)
        #pragma unroll
        for (int ks = 0; ks < 8; ks++) {
            int rA = ks * 16 + (lane & 7) + ((lane >> 4) & 1) * 8;
            uint32_t ah[2][4], al[2][4];
            #pragma unroll
            for (int t = 0; t < 2; t++) {
                int dseg = wm * 32 + t * 16 + ((lane >> 3) & 1) * 8;
                uint32_t addr = sal + CB_SAH + ((uint32_t)(dseg >> 6) << 14) +
                    SW128((uint32_t)(rA * 128 + (dseg & 63) * 2));
                ldsm4t(ah[t], addr);
                ldsm4t(al[t], addr + 32768);
            }
            int rB = ks * 16 + (lane & 7) + ((lane >> 3) & 1) * 8;
            #pragma unroll
            for (int eg = 0; eg < 4; eg++) {
                int eseg = wn * 64 + eg * 16 + ((lane >> 4) & 1) * 8;
                uint32_t baddr = sal + DVB + ((uint32_t)(eseg >> 6) << 14) +
                    SW128((uint32_t)(rB * 128 + (eseg & 63) * 2));
                uint32_t bh[4], bl[4];
                ldsm4t(bh, baddr);
                ldsm4t(bl, baddr + 32768);
                #pragma unroll
                for (int t = 0; t < 2; t++) mma_bf16(pac[t][eg * 2 + 0], ah[t], bh);
                #pragma unroll
                for (int t = 0; t < 2; t++) mma_bf16(pac[t][eg * 2 + 1], ah[t], bh + 2);
                #pragma unroll
                for (int t = 0; t < 2; t++) mma_bf16(pac[t][eg * 2 + 0], ah[t], bl);
                #pragma unroll
                for (int t = 0; t < 2; t++) mma_bf16(pac[t][eg * 2 + 1], ah[t], bl + 2);
                #pragma unroll
                for (int t = 0; t < 2; t++) mma_bf16(pac[t][eg * 2 + 0], al[t], bh);
                #pragma unroll
                for (int t = 0; t < 2; t++) mma_bf16(pac[t][eg * 2 + 1], al[t], bh + 2);
            }
        }
    }

    size_t base = ((size_t)(h * 64 + bx)) << 14;   // 128x128 floats per slice
    #pragma unroll
    for (int t = 0; t < 2; t++) {
        int d0 = wm * 32 + t * 16 + (lane >> 2);
        #pragma unroll
        for (int j = 0; j < 8; j++) {
            int col = wn * 64 + j * 8 + (lane & 3) * 2;
            *(float2*)&part[base + (size_t)d0 * 128 + col]       = make_float2(pac[t][j][0], pac[t][j][1]);
            *(float2*)&part[base + (size_t)(d0 + 8) * 128 + col] = make_float2(pac[t][j][2], pac[t][j][3]);
        }
    }
}

// ===================== reductions =====================
__global__ void reduce_mem_kernel(const float* __restrict__ part,
                                  const float* __restrict__ memories,
                                  float* __restrict__ out)
{
    int t = blockIdx.x * blockDim.x + threadIdx.x;
    int h = t >> 14;
    int rem = t & 16383;
    float s = 0.f;
    #pragma unroll 8
    for (int sl = 0; sl < 64; sl++)
        s += part[((size_t)(h * 64 + sl) << 14) + rem];
    out[OUT_MEM + t] = memories[(size_t)h * DD * DD + rem] + s * (1.f / (float)BQ);
}

__global__ void reduce_norm_kernel(const float* __restrict__ nsum,
                                   const float* __restrict__ mnorms,
                                   float* __restrict__ out)
{
    int t = blockIdx.x * blockDim.x + threadIdx.x;
    int h = t >> 7, d = t & 127;
    float s = 0.f;
    for (int b = 0; b < 128; b++)
        s += nsum[(size_t)(h * 128 + b) * DD + d];
    out[OUT_NORM + t] = mnorms[(size_t)h * DD + d] + s * 0.25f;
}

// ---------------------------------------------------------------------------
extern "C" void kernel_launch(void* const* d_in, const int* in_sizes, int n_in,
                              void* d_out, int out_size)
{
    const float* hs = (const float*)d_in[0];
    const float* Wq = (const float*)d_in[1];
    const float* Wk = (const float*)d_in[2];
    const float* Wv = (const float*)d_in[3];
    const float* Wo = (const float*)d_in[4];
    const float* bw = (const float*)d_in[5];
    const float* mem = (const float*)d_in[6];
    const float* mnm = (const float*)d_in[7];
    float* out = (float*)d_out;

    float *pqkv, *ppart, *pnsum;
    __nv_bfloat16 *hsh, *hsl, *wh, *wl, *cbh, *cbl, *mTh, *mTl, *nTh, *nTl;
    cudaGetSymbolAddress((void**)&pqkv, g_qkv);
    cudaGetSymbolAddress((void**)&ppart, g_part);
    cudaGetSymbolAddress((void**)&pnsum, g_nsum);
    cudaGetSymbolAddress((void**)&hsh, g_hs_hi);
    cudaGetSymbolAddress((void**)&hsl, g_hs_lo);
    cudaGetSymbolAddress((void**)&wh, g_w_hi);
    cudaGetSymbolAddress((void**)&wl, g_w_lo);
    cudaGetSymbolAddress((void**)&cbh, g_cb_hi);
    cudaGetSymbolAddress((void**)&cbl, g_cb_lo);
    cudaGetSymbolAddress((void**)&mTh, g_mTh);
    cudaGetSymbolAddress((void**)&mTl, g_mTl);
    cudaGetSymbolAddress((void**)&nTh, g_nTh);
    cudaGetSymbolAddress((void**)&nTl, g_nTl);

    static int smem_set = 0;
    if (!smem_set) {
        cudaFuncSetAttribute(hgemm_kernel, cudaFuncAttributeMaxDynamicSharedMemorySize, HG_SMEM);
        cudaFuncSetAttribute(combined_hmma, cudaFuncAttributeMaxDynamicSharedMemorySize, CB_SMEM);
        cudaFuncSetAttribute(deltav_hmma, cudaFuncAttributeMaxDynamicSharedMemorySize, CB_SMEM);
        smem_set = 1;
    }

    const size_t WSZ = (size_t)HIDC * HIDC;

    prep_kernel<<<1, 128>>>(bw, mnm);
    cvt_split_kernel<<<(BQ * (size_t)HIDC) / 4 / 256, 256>>>(hs, hsh, hsl);
    cvt_split_kernel<<<WSZ / 4 / 256, 256>>>(Wq, wh + 0 * WSZ, wl + 0 * WSZ);
    cvt_split_kernel<<<WSZ / 4 / 256, 256>>>(Wk, wh + 1 * WSZ, wl + 1 * WSZ);
    cvt_split_kernel<<<WSZ / 4 / 256, 256>>>(Wv, wh + 2 * WSZ, wl + 2 * WSZ);

    // fused QKV GEMM: B rows = [Wq|Wk|Wv] (contiguous), N = 6144
    hgemm_kernel<<<dim3(QKVW / 256, BQ / 128), 256, HG_SMEM>>>(hsh, hsl, wh, wl, pqkv, QKVW);

    cvt_split_kernel<<<WSZ / 4 / 256, 256>>>(Wo, wh + 3 * WSZ, wl + 3 * WSZ);
    prep2_kernel<<<NBANK * NH, 256>>>(mem, mTh, mTl);
    normt_kernel<<<NH, 256>>>(mnm, nTh, nTl);

    combined_hmma<<<dim3(BQ / 128, NH), 256, CB_SMEM>>>(pqkv, mTh, mTl, nTh, nTl, cbh, cbl);
    deltav_hmma<<<dim3(BQ / 256, NH), 256, CB_SMEM>>>(pqkv, mTh, mTl, nTh, nTl, pnsum, ppart);

    reduce_mem_kernel<<<(NH * DD * DD) / 256, 256>>>(ppart, mem, out);
    reduce_norm_kernel<<<(NH * DD) / 256, 256>>>(pnsum, mnm, out);

    hgemm_kernel<<<dim3(HIDC / 256, BQ / 128), 256, HG_SMEM>>>(cbh, cbl, wh + 3 * WSZ, wl + 3 * WSZ, out, HIDC);
}

// round 16
// speedup vs baseline: 1.0581x; 1.0581x over previous
#include <cuda_runtime.h>
#include <cuda_bf16.h>
#include <math.h>
#include <stdint.h>

// Problem constants
#define BQ   16384          // B*S rows
#define HIDC 2048
#define NH   16
#define DD   128
#define NBANK 4
#define EPSF 1e-6f
#define GK   2048
#define QKVW 6144           // fused qkv row width

#define OUT_MEM  ((size_t)BQ * HIDC)
#define OUT_NORM (OUT_MEM + (size_t)NH * DD * DD)

// -------- scratch (static device globals; no runtime allocation) ----------
__device__ float g_qkv[(size_t)BQ * QKVW];            // fused q|k|v projections
__device__ float g_part[(size_t)NH * 64 * DD * DD];   // mem-update partials (64 slices)
__device__ float g_nsum[(size_t)NH * 128 * DD];
__device__ float g_weff[NH][NBANK];

// tf32-rounded fp32 operands for the QKV GEMM
__device__ float g_hsr[(size_t)BQ * HIDC];
__device__ float g_wr[(size_t)3 * HIDC * HIDC];       // Wq|Wk|Wv rounded

// bf16 hi/lo buffers (output GEMM path)
__device__ __nv_bfloat16 g_wo_hi[(size_t)HIDC * HIDC];
__device__ __nv_bfloat16 g_wo_lo[(size_t)HIDC * HIDC];
__device__ __nv_bfloat16 g_cb_hi[(size_t)BQ * HIDC];  // combined hi/lo
__device__ __nv_bfloat16 g_cb_lo[(size_t)BQ * HIDC];

// pre-swizzled transposed memories (B-operand layout) + norm tiles
__device__ __nv_bfloat16 g_mTh[(size_t)NBANK * NH * DD * DD];
__device__ __nv_bfloat16 g_mTl[(size_t)NBANK * NH * DD * DD];
__device__ __nv_bfloat16 g_nTh[(size_t)NH * 1024];
__device__ __nv_bfloat16 g_nTl[(size_t)NH * 1024];

__device__ __forceinline__ float sigf(float x) { return x > 0.f ? x + 1.f : expf(x); }

__device__ __forceinline__ uint32_t smem_to_u32(const void* p) {
    uint32_t a;
    asm("{ .reg .u64 t; cvta.to.shared.u64 t, %1; cvt.u32.u64 %0, t; }" : "=r"(a) : "l"(p));
    return a;
}
#define SW128(off) ((off) ^ (((off) >> 3) & 0x70))

__device__ __forceinline__ void cp_async16(uint32_t saddr, const void* gaddr) {
    asm volatile("cp.async.cg.shared.global [%0], [%1], 16;" :: "r"(saddr), "l"(gaddr));
}
__device__ __forceinline__ void cp_commit() {
    asm volatile("cp.async.commit_group;" ::: "memory");
}
__device__ __forceinline__ void ldsm4(uint32_t* r, uint32_t addr) {
    asm volatile("ldmatrix.sync.aligned.m8n8.x4.shared.b16 {%0,%1,%2,%3}, [%4];"
        : "=r"(r[0]), "=r"(r[1]), "=r"(r[2]), "=r"(r[3]) : "r"(addr));
}
__device__ __forceinline__ void ldsm4t(uint32_t* r, uint32_t addr) {
    asm volatile("ldmatrix.sync.aligned.m8n8.x4.trans.shared.b16 {%0,%1,%2,%3}, [%4];"
        : "=r"(r[0]), "=r"(r[1]), "=r"(r[2]), "=r"(r[3]) : "r"(addr));
}
__device__ __forceinline__ void ldsm2(uint32_t* r, uint32_t addr) {
    asm volatile("ldmatrix.sync.aligned.m8n8.x2.shared.b16 {%0,%1}, [%2];"
        : "=r"(r[0]), "=r"(r[1]) : "r"(addr));
}
__device__ __forceinline__ void mma_bf16(float* c, const uint32_t* a, const uint32_t* b) {
    asm volatile("mma.sync.aligned.m16n8k16.row.col.f32.bf16.bf16.f32 "
        "{%0,%1,%2,%3}, {%4,%5,%6,%7}, {%8,%9}, {%0,%1,%2,%3};"
        : "+f"(c[0]), "+f"(c[1]), "+f"(c[2]), "+f"(c[3])
        : "r"(a[0]), "r"(a[1]), "r"(a[2]), "r"(a[3]), "r"(b[0]), "r"(b[1]));
}
__device__ __forceinline__ void mma_tf32(float* c, const uint32_t* a, const uint32_t* b) {
    asm volatile("mma.sync.aligned.m16n8k8.row.col.f32.tf32.tf32.f32 "
        "{%0,%1,%2,%3}, {%4,%5,%6,%7}, {%8,%9}, {%0,%1,%2,%3};"
        : "+f"(c[0]), "+f"(c[1]), "+f"(c[2]), "+f"(c[3])
        : "r"(a[0]), "r"(a[1]), "r"(a[2]), "r"(a[3]), "r"(b[0]), "r"(b[1]));
}
__device__ __forceinline__ uint32_t to_tf32(float x) {
    uint32_t r;
    asm("cvt.rna.tf32.f32 %0, %1;" : "=r"(r) : "f"(x));
    return r;
}

// ===================== rounding / split conversions =====================
__global__ void cvt_round_kernel(const float* __restrict__ x, float* __restrict__ o)
{
    size_t i = ((size_t)blockIdx.x * blockDim.x + threadIdx.x) * 4;
    float4 v = *(const float4*)(x + i);
    uint4 r;
    r.x = to_tf32(v.x); r.y = to_tf32(v.y); r.z = to_tf32(v.z); r.w = to_tf32(v.w);
    *(uint4*)(o + i) = r;
}

__global__ void cvt_split_kernel(const float* __restrict__ x,
                                 __nv_bfloat16* __restrict__ hi,
                                 __nv_bfloat16* __restrict__ lo)
{
    size_t i = ((size_t)blockIdx.x * blockDim.x + threadIdx.x) * 4;
    float4 v = *(const float4*)(x + i);
    __nv_bfloat16 h0 = __float2bfloat16(v.x), h1 = __float2bfloat16(v.y);
    __nv_bfloat16 h2 = __float2bfloat16(v.z), h3 = __float2bfloat16(v.w);
    __nv_bfloat16 l0 = __float2bfloat16(v.x - __bfloat162float(h0));
    __nv_bfloat16 l1 = __float2bfloat16(v.y - __bfloat162float(h1));
    __nv_bfloat16 l2 = __float2bfloat16(v.z - __bfloat162float(h2));
    __nv_bfloat16 l3 = __float2bfloat16(v.w - __bfloat162float(h3));
    __nv_bfloat162* ph = (__nv_bfloat162*)(hi + i);
    __nv_bfloat162* pl = (__nv_bfloat162*)(lo + i);
    ph[0] = __nv_bfloat162(h0, h1); ph[1] = __nv_bfloat162(h2, h3);
    pl[0] = __nv_bfloat162(l0, l1); pl[1] = __nv_bfloat162(l2, l3);
}

// ===================== TF32 GEMM: C[M,N] = A[M,K] @ B[N,K]^T =====================
// fp32 (tf32-rounded) operands, single pass. Block 128m x 256n, warp 64x64,
// K-chunk 32, 3-stage cp.async. Padded smem stride 36 floats (conflict-free).
#define T32_STRIDE 36
#define T32_AS (128 * T32_STRIDE * 4)            // 18432 B
#define T32_BS (256 * T32_STRIDE * 4)            // 36864 B
#define T32_STG (T32_AS + T32_BS)                // 55296 B
#define T32_NCH 64                               // K / 32
#define T32_SMEM (3 * T32_STG + 1024)

__device__ __forceinline__ void t32_load_stage(
    const float* __restrict__ A, const float* __restrict__ B,
    uint32_t sb, int bm, int bn, int k0, int tid)
{
    #pragma unroll
    for (int it = 0; it < 4; it++) {
        int id = tid + it * 256;            // 0..1023 : A rows 0..127
        int r = id >> 3, c = id & 7;
        cp_async16(sb + (uint32_t)(r * T32_STRIDE + c * 4) * 4,
                   A + (size_t)(bm + r) * GK + k0 + c * 4);
    }
    #pragma unroll
    for (int it = 0; it < 8; it++) {
        int id = tid + it * 256;            // 0..2047 : B rows 0..255
        int r = id >> 3, c = id & 7;
        cp_async16(sb + T32_AS + (uint32_t)(r * T32_STRIDE + c * 4) * 4,
                   B + (size_t)(bn + r) * GK + k0 + c * 4);
    }
}

__global__ __launch_bounds__(256, 1)
void tgemm32_kernel(const float* __restrict__ A, const float* __restrict__ B,
                    float* __restrict__ C, int N)
{
    extern __shared__ char smem[];
    uint32_t sraw = smem_to_u32(smem);
    uint32_t sal = (sraw + 1023u) & ~1023u;
    const uint32_t* sm32 = (const uint32_t*)(smem + (sal - sraw));

    int tid = threadIdx.x;
    int lane = tid & 31, wid = tid >> 5;
    int wm = wid >> 2, wn = wid & 3;        // warp tile 64m x 64n
    int bm = blockIdx.y * 128;
    int bn = blockIdx.x * 256;
    int grp = lane >> 2, tig = lane & 3;

    float acc[4][8][4];
    #pragma unroll
    for (int t = 0; t < 4; t++)
        #pragma unroll
        for (int n = 0; n < 8; n++)
            #pragma unroll
            for (int j = 0; j < 4; j++) acc[t][n][j] = 0.f;

    t32_load_stage(A, B, sal, bm, bn, 0, tid);
    cp_commit();
    t32_load_stage(A, B, sal + T32_STG, bm, bn, 32, tid);
    cp_commit();

    for (int c = 0; c < T32_NCH; c++) {
        if (c == T32_NCH - 1) { asm volatile("cp.async.wait_group 0;" ::: "memory"); }
        else                  { asm volatile("cp.async.wait_group 1;" ::: "memory"); }
        __syncthreads();
        const uint32_t* sA = sm32 + ((c % 3) * T32_STG >> 2);
        const uint32_t* sB = sA + (T32_AS >> 2);

        #pragma unroll
        for (int ks = 0; ks < 4; ks++) {
            int col0 = ks * 8 + tig;
            uint32_t af[4][4];
            #pragma unroll
            for (int t = 0; t < 4; t++) {
                int r0 = wm * 64 + t * 16 + grp;
                af[t][0] = sA[r0 * T32_STRIDE + col0];
                af[t][1] = sA[(r0 + 8) * T32_STRIDE + col0];
                af[t][2] = sA[r0 * T32_STRIDE + col0 + 4];
                af[t][3] = sA[(r0 + 8) * T32_STRIDE + col0 + 4];
            }
            #pragma unroll
            for (int ng = 0; ng < 8; ng++) {
                int bn0 = wn * 64 + ng * 8 + grp;
                uint32_t bf[2];
                bf[0] = sB[bn0 * T32_STRIDE + ks * 8 + tig];
                bf[1] = sB[bn0 * T32_STRIDE + ks * 8 + tig + 4];
                #pragma unroll
                for (int t = 0; t < 4; t++) mma_tf32(acc[t][ng], af[t], bf);
            }
        }
        __syncthreads();
        if (c + 2 < T32_NCH) {
            t32_load_stage(A, B, sal + ((c + 2) % 3) * T32_STG, bm, bn, (c + 2) * 32, tid);
            cp_commit();
        }
    }

    #pragma unroll
    for (int t = 0; t < 4; t++) {
        int r0 = bm + wm * 64 + t * 16 + grp;
        #pragma unroll
        for (int ng = 0; ng < 8; ng++) {
            int col = bn + wn * 64 + ng * 8 + tig * 2;
            *(float2*)&C[(size_t)r0 * N + col]       = make_float2(acc[t][ng][0], acc[t][ng][1]);
            *(float2*)&C[(size_t)(r0 + 8) * N + col] = make_float2(acc[t][ng][2], acc[t][ng][3]);
        }
    }
}

// ===================== HMMA GEMM (bf16 hi/lo 3-pass) — output projection =====================
#define SA_H 0
#define SA_L 16384
#define SB_H 32768
#define SB_L 65536
#define STG2 98304
#define NCHUNK 32           // K / 64
#define HG_SMEM (2 * STG2 + 1024)

__device__ __forceinline__ void load_stage(
    const __nv_bfloat16* __restrict__ Ah, const __nv_bfloat16* __restrict__ Al,
    const __nv_bfloat16* __restrict__ Bh, const __nv_bfloat16* __restrict__ Bl,
    uint32_t sb, int bm, int bn, int k0, int tid)
{
    #pragma unroll
    for (int it = 0; it < 4; it++) {
        int id = tid + it * 256;
        int r = id >> 3, c = id & 7;
        uint32_t sw = SW128((uint32_t)(r * 128 + c * 16));
        size_t ga = (size_t)(bm + r) * GK + k0 + c * 8;
        cp_async16(sb + SA_H + sw, Ah + ga);
        cp_async16(sb + SA_L + sw, Al + ga);
    }
    #pragma unroll
    for (int it = 0; it < 8; it++) {
        int id = tid + it * 256;
        int r = id >> 3, c = id & 7;
        uint32_t sw = SW128((uint32_t)(r * 128 + c * 16));
        size_t gb = (size_t)(bn + r) * GK + k0 + c * 8;
        cp_async16(sb + SB_H + sw, Bh + gb);
        cp_async16(sb + SB_L + sw, Bl + gb);
    }
}

__global__ __launch_bounds__(256, 1)
void hgemm_kernel(const __nv_bfloat16* __restrict__ Ah, const __nv_bfloat16* __restrict__ Al,
                  const __nv_bfloat16* __restrict__ Bh, const __nv_bfloat16* __restrict__ Bl,
                  float* __restrict__ C, int N)
{
    extern __shared__ char smem[];
    uint32_t sraw = smem_to_u32(smem);
    uint32_t sal = (sraw + 1023u) & ~1023u;

    int tid = threadIdx.x;
    int lane = tid & 31, wid = tid >> 5;
    int wm = wid >> 2, wn = wid & 3;
    int bm = blockIdx.y * 128;
    int bn = blockIdx.x * 256;

    float acc[4][8][4];
    #pragma unroll
    for (int t = 0; t < 4; t++)
        #pragma unroll
        for (int n = 0; n < 8; n++)
            #pragma unroll
            for (int j = 0; j < 4; j++) acc[t][n][j] = 0.f;

    load_stage(Ah, Al, Bh, Bl, sal, bm, bn, 0, tid);
    cp_commit();
    load_stage(Ah, Al, Bh, Bl, sal + STG2, bm, bn, 64, tid);
    cp_commit();

    uint32_t a_base = (uint32_t)((wm * 64 + (lane & 15)) * 128 + (lane >> 4) * 16);
    uint32_t b_base = (uint32_t)((wn * 64 + ((lane >> 4) << 3) + (lane & 7)) * 128 +
                                 ((lane >> 3) & 1) * 16);

    for (int c = 0; c < NCHUNK; c++) {
        if (c == NCHUNK - 1) { asm volatile("cp.async.wait_group 0;" ::: "memory"); }
        else                 { asm volatile("cp.async.wait_group 1;" ::: "memory"); }
        __syncthreads();
        uint32_t sb = sal + (c & 1) * STG2;

        #pragma unroll
        for (int ks = 0; ks < 4; ks++) {
            uint32_t ah[4][4], al[4][4];
            #pragma unroll
            for (int t = 0; t < 4; t++) {
                uint32_t aaddr = sb + SA_H + SW128(a_base + t * 16 * 128 + ks * 32);
                ldsm4(ah[t], aaddr);
                ldsm4(al[t], aaddr + (SA_L - SA_H));
            }
            #pragma unroll
            for (int ng = 0; ng < 4; ng++) {
                uint32_t baddr = sb + SB_H + SW128(b_base + ng * 16 * 128 + ks * 32);
                uint32_t bh[4], bl[4];
                ldsm4(bh, baddr);
                ldsm4(bl, baddr + (SB_L - SB_H));
                #pragma unroll
                for (int t = 0; t < 4; t++) mma_bf16(acc[t][ng * 2 + 0], ah[t], bh);
                #pragma unroll
                for (int t = 0; t < 4; t++) mma_bf16(acc[t][ng * 2 + 1], ah[t], bh + 2);
                #pragma unroll
                for (int t = 0; t < 4; t++) mma_bf16(acc[t][ng * 2 + 0], ah[t], bl);
                #pragma unroll
                for (int t = 0; t < 4; t++) mma_bf16(acc[t][ng * 2 + 1], ah[t], bl + 2);
                #pragma unroll
                for (int t = 0; t < 4; t++) mma_bf16(acc[t][ng * 2 + 0], al[t], bh);
                #pragma unroll
                for (int t = 0; t < 4; t++) mma_bf16(acc[t][ng * 2 + 1], al[t], bh + 2);
            }
        }
        __syncthreads();
        if (c + 2 < NCHUNK) {
            load_stage(Ah, Al, Bh, Bl, sal + (c & 1) * STG2, bm, bn, (c + 2) * 64, tid);
            cp_commit();
        }
    }

    #pragma unroll
    for (int t = 0; t < 4; t++) {
        int r0 = bm + wm * 64 + t * 16 + (lane >> 2);
        #pragma unroll
        for (int nt = 0; nt < 8; nt++) {
            int col = bn + wn * 64 + nt * 8 + (lane & 3) * 2;
            *(float2*)&C[(size_t)r0 * N + col]       = make_float2(acc[t][nt][0], acc[t][nt][1]);
            *(float2*)&C[(size_t)(r0 + 8) * N + col] = make_float2(acc[t][nt][2], acc[t][nt][3]);
        }
    }
}

// ===================== K0: softmax of bank weights + active flags =====================
__global__ void prep_kernel(const float* __restrict__ bw, const float* __restrict__ mn) {
    __shared__ float bsum[NBANK];
    int tid = threadIdx.x;
    int w = tid >> 5, lane = tid & 31;
    if (w < NBANK) {
        float s = 0.f;
        for (int i = lane; i < NH * DD; i += 32) s += mn[w * NH * DD + i];
        #pragma unroll
        for (int o = 16; o; o >>= 1) s += __shfl_down_sync(0xffffffffu, s, o);
        if (lane == 0) bsum[w] = s;
    }
    __syncthreads();
    if (tid < NH) {
        float x0 = bw[tid * 4 + 0], x1 = bw[tid * 4 + 1];
        float x2 = bw[tid * 4 + 2], x3 = bw[tid * 4 + 3];
        float m = fmaxf(fmaxf(x0, x1), fmaxf(x2, x3));
        float e0 = expf(x0 - m), e1 = expf(x1 - m), e2 = expf(x2 - m), e3 = expf(x3 - m);
        float inv = 1.f / (e0 + e1 + e2 + e3);
        g_weff[tid][0] = e0 * inv * (bsum[0] >= EPSF ? 1.f : 0.f);
        g_weff[tid][1] = e1 * inv * (bsum[1] >= EPSF ? 1.f : 0.f);
        g_weff[tid][2] = e2 * inv * (bsum[2] >= EPSF ? 1.f : 0.f);
        g_weff[tid][3] = e3 * inv * (bsum[3] >= EPSF ? 1.f : 0.f);
    }
}

// ===================== prep2: memories -> transposed, split, pre-swizzled =====================
__global__ void prep2_kernel(const float* __restrict__ mem,
                             __nv_bfloat16* __restrict__ mTh, __nv_bfloat16* __restrict__ mTl)
{
    int nh = blockIdx.x;     // 0..63
    const float* src = mem + (size_t)nh * 16384;
    __nv_bfloat16* dh = mTh + (size_t)nh * 16384;
    __nv_bfloat16* dl = mTl + (size_t)nh * 16384;
    for (int i = threadIdx.x; i < 16384; i += 256) {
        int d = i >> 7, e = i & 127;
        float v = src[d * 128 + e];
        __nv_bfloat16 hi = __float2bfloat16(v);
        __nv_bfloat16 lo = __float2bfloat16(v - __bfloat162float(hi));
        uint32_t off = ((uint32_t)(d >> 6) << 13) +
                       (SW128((uint32_t)(e * 128 + (d & 63) * 2)) >> 1);
        dh[off] = hi; dl[off] = lo;
    }
}

__global__ void normt_kernel(const float* __restrict__ mnm,
                             __nv_bfloat16* __restrict__ nTh, __nv_bfloat16* __restrict__ nTl)
{
    int h = blockIdx.x;
    for (int i = threadIdx.x; i < 1024; i += 256) {
        int nr = i >> 7, d = i & 127;
        float v = (nr < NBANK) ? mnm[(size_t)(nr * NH + h) * DD + d] : 0.f;
        __nv_bfloat16 hi = __float2bfloat16(v);
        __nv_bfloat16 lo = __float2bfloat16(v - __bfloat162float(hi));
        uint32_t off = ((uint32_t)(d >> 6) << 9) +
                       (SW128((uint32_t)(nr * 128 + (d & 63) * 2)) >> 1);
        nTh[h * 1024 + off] = hi; nTl[h * 1024 + off] = lo;
    }
}

// ===================== HMMA combined / deltav =====================
#define CB_SAH   0
#define CB_SAL   32768
#define CB_SB    65536
#define CB_SNTH  196608
#define CB_SNTL  198656
#define CB_SNORM 200704
#define CB_SCOEF 202752
#define CB_SSUM  204800
#define CB_SMEM  207872

__device__ __forceinline__ void sigma_to_smem(const float* __restrict__ src, int row0,
                                              int colbase, int stride, char* sb, int tid)
{
    #pragma unroll
    for (int i = 0; i < 16; i++) {
        int id = tid + i * 256;
        int r = id >> 5, c4 = id & 31;
        float4 v = *(const float4*)&src[(size_t)(row0 + r) * stride + colbase + c4 * 4];
        float s0 = sigf(v.x), s1 = sigf(v.y), s2 = sigf(v.z), s3 = sigf(v.w);
        __nv_bfloat16 h0 = __float2bfloat16(s0), h1 = __float2bfloat16(s1);
        __nv_bfloat16 h2 = __float2bfloat16(s2), h3 = __float2bfloat16(s3);
        __nv_bfloat16 l0 = __float2bfloat16(s0 - __bfloat162float(h0));
        __nv_bfloat16 l1 = __float2bfloat16(s1 - __bfloat162float(h1));
        __nv_bfloat16 l2 = __float2bfloat16(s2 - __bfloat162float(h2));
        __nv_bfloat16 l3 = __float2bfloat16(s3 - __bfloat162float(h3));
        int d0 = c4 * 4;
        uint32_t off = (uint32_t)((d0 >> 6) * 16384) + SW128((uint32_t)(r * 128 + (d0 & 63) * 2));
        *(__nv_bfloat162*)(sb + CB_SAH + off)     = __nv_bfloat162(h0, h1);
        *(__nv_bfloat162*)(sb + CB_SAH + off + 4) = __nv_bfloat162(h2, h3);
        *(__nv_bfloat162*)(sb + CB_SAL + off)     = __nv_bfloat162(l0, l1);
        *(__nv_bfloat162*)(sb + CB_SAL + off + 4) = __nv_bfloat162(l2, l3);
    }
}

__device__ __forceinline__ void norm_mma(uint32_t sal, char* sb, int wm, int lane)
{
    float nc[2][4];
    #pragma unroll
    for (int t = 0; t < 2; t++)
        #pragma unroll
        for (int j = 0; j < 4; j++) nc[t][j] = 0.f;
    #pragma unroll
    for (int ks = 0; ks < 8; ks++) {
        uint32_t ah[2][4], al[2][4];
        #pragma unroll
        for (int t = 0; t < 2; t++) {
            uint32_t aaddr = sal + CB_SAH + (ks >> 2) * 16384 +
                SW128((uint32_t)((wm * 32 + t * 16 + (lane & 15)) * 128 + (ks & 3) * 32 + (lane >> 4) * 16));
            ldsm4(ah[t], aaddr);
            ldsm4(al[t], aaddr + 32768);
        }
        uint32_t bh[2], bl[2];
        uint32_t naddr = sal + CB_SNTH + (ks >> 2) * 1024 +
            SW128((uint32_t)((lane & 7) * 128 + (ks & 3) * 32 + ((lane >> 3) & 1) * 16));
        ldsm2(bh, naddr);
        ldsm2(bl, naddr + 2048);
        #pragma unroll
        for (int t = 0; t < 2; t++) mma_bf16(nc[t], ah[t], bh);
        #pragma unroll
        for (int t = 0; t < 2; t++) mma_bf16(nc[t], al[t], bh);
        #pragma unroll
        for (int t = 0; t < 2; t++) mma_bf16(nc[t], ah[t], bl);
    }
    float* sN = (float*)(sb + CB_SNORM);
    if ((lane & 3) < 2) {
        #pragma unroll
        for (int t = 0; t < 2; t++) {
            int rr = wm * 32 + t * 16 + (lane >> 2);
            sN[rr * 4 + (lane & 3) * 2]           = nc[t][0];
            sN[rr * 4 + (lane & 3) * 2 + 1]       = nc[t][1];
            sN[(rr + 8) * 4 + (lane & 3) * 2]     = nc[t][2];
            sN[(rr + 8) * 4 + (lane & 3) * 2 + 1] = nc[t][3];
        }
    }
}

__device__ __forceinline__ void bank_mma(uint32_t sal, uint32_t sbB, int wm, int wn, int lane,
                                         float acc[2][8][4])
{
    #pragma unroll
    for (int ks = 0; ks < 8; ks++) {
        uint32_t ah[2][4], al[2][4];
        #pragma unroll
        for (int t = 0; t < 2; t++) {
            uint32_t aaddr = sal + CB_SAH + (ks >> 2) * 16384 +
                SW128((uint32_t)((wm * 32 + t * 16 + (lane & 15)) * 128 + (ks & 3) * 32 + (lane >> 4) * 16));
            ldsm4(ah[t], aaddr);
            ldsm4(al[t], aaddr + 32768);
        }
        #pragma unroll
        for (int nt = 0; nt < 4; nt++) {
            uint32_t baddr = sbB + (ks >> 2) * 16384 +
                SW128((uint32_t)((wn * 64 + nt * 16 + ((lane >> 4) << 3) + (lane & 7)) * 128 +
                                 (ks & 3) * 32 + ((lane >> 3) & 1) * 16));
            uint32_t bh[4], bl[4];
            ldsm4(bh, baddr);
            ldsm4(bl, baddr + 32768);
            #pragma unroll
            for (int t = 0; t < 2; t++) mma_bf16(acc[t][nt * 2 + 0], ah[t], bh);
            #pragma unroll
            for (int t = 0; t < 2; t++) mma_bf16(acc[t][nt * 2 + 1], ah[t], bh + 2);
            #pragma unroll
            for (int t = 0; t < 2; t++) mma_bf16(acc[t][nt * 2 + 0], ah[t], bl);
            #pragma unroll
            for (int t = 0; t < 2; t++) mma_bf16(acc[t][nt * 2 + 1], ah[t], bl + 2);
            #pragma unroll
            for (int t = 0; t < 2; t++) mma_bf16(acc[t][nt * 2 + 0], al[t], bh);
            #pragma unroll
            for (int t = 0; t < 2; t++) mma_bf16(acc[t][nt * 2 + 1], al[t], bh + 2);
        }
    }
}

__device__ __forceinline__ void copy_bank(const __nv_bfloat16* mTh, const __nv_bfloat16* mTl,
                                          int n, int h, int buf, uint32_t sal, int tid)
{
    const __nv_bfloat16* sh = mTh + ((size_t)(n * NH + h) << 14);
    const __nv_bfloat16* sl = mTl + ((size_t)(n * NH + h) << 14);
    uint32_t dst = sal + CB_SB + buf * 65536;
    #pragma unroll
    for (int i = 0; i < 8; i++) {
        int id = tid + i * 256;
        cp_async16(dst + id * 16, sh + id * 8);
        cp_async16(dst + 32768 + id * 16, sl + id * 8);
    }
}

__global__ __launch_bounds__(256, 1) void combined_hmma(
    const float* __restrict__ qkv,
    const __nv_bfloat16* __restrict__ mTh, const __nv_bfloat16* __restrict__ mTl,
    const __nv_bfloat16* __restrict__ nTh, const __nv_bfloat16* __restrict__ nTl,
    __nv_bfloat16* __restrict__ cbh, __nv_bfloat16* __restrict__ cbl)
{
    extern __shared__ char smem[];
    uint32_t sraw = smem_to_u32(smem);
    uint32_t sal = (sraw + 1023u) & ~1023u;
    char* sb = smem + (sal - sraw);
    int tid = threadIdx.x, lane = tid & 31, wid = tid >> 5;
    int wm = wid & 3, wn = wid >> 2;
    int h = blockIdx.y;
    int row0 = blockIdx.x * 128;

    copy_bank(mTh, mTl, 0, h, 0, sal, tid);
    if (tid < 128) {
        cp_async16(sal + CB_SNTH + tid * 16, nTh + h * 1024 + tid * 8);
        cp_async16(sal + CB_SNTL + tid * 16, nTl + h * 1024 + tid * 8);
    }
    cp_commit();
    copy_bank(mTh, mTl, 1, h, 1, sal, tid);
    cp_commit();

    sigma_to_smem(qkv, row0, h * DD, QKVW, sb, tid);   // q columns
    __syncthreads();

    asm volatile("cp.async.wait_group 1;" ::: "memory");
    __syncthreads();
    if (wn == 0) norm_mma(sal, sb, wm, lane);
    __syncthreads();

    float* sN = (float*)(sb + CB_SNORM);
    float* sC = (float*)(sb + CB_SCOEF);
    {
        int rr = tid >> 1, base = (tid & 1) * 2;
        sC[rr * 4 + base]     = g_weff[h][base]     / fmaxf(sN[rr * 4 + base], EPSF);
        sC[rr * 4 + base + 1] = g_weff[h][base + 1] / fmaxf(sN[rr * 4 + base + 1], EPSF);
    }
    __syncthreads();

    float fin[2][8][4];
    #pragma unroll
    for (int t = 0; t < 2; t++)
        #pragma unroll
        for (int j = 0; j < 8; j++)
            #pragma unroll
            for (int p = 0; p < 4; p++) fin[t][j][p] = 0.f;

    for (int n = 0; n < NBANK; n++) {
        if (n < 3) { asm volatile("cp.async.wait_group 1;" ::: "memory"); }
        else       { asm volatile("cp.async.wait_group 0;" ::: "memory"); }
        __syncthreads();
        float acc[2][8][4];
        #pragma unroll
        for (int t = 0; t < 2; t++)
            #pragma unroll
            for (int j = 0; j < 8; j++)
                #pragma unroll
                for (int p = 0; p < 4; p++) acc[t][j][p] = 0.f;
        bank_mma(sal, sal + CB_SB + (n & 1) * 65536, wm, wn, lane, acc);
        __syncthreads();
        if (n + 2 < NBANK) { copy_bank(mTh, mTl, n + 2, h, n & 1, sal, tid); cp_commit(); }
        #pragma unroll
        for (int t = 0; t < 2; t++) {
            int rrA = wm * 32 + t * 16 + (lane >> 2);
            float cA = sC[rrA * 4 + n], cB = sC[(rrA + 8) * 4 + n];
            #pragma unroll
            for (int j = 0; j < 8; j++) {
                fin[t][j][0] += cA * acc[t][j][0];
                fin[t][j][1] += cA * acc[t][j][1];
                fin[t][j][2] += cB * acc[t][j][2];
                fin[t][j][3] += cB * acc[t][j][3];
            }
        }
    }

    #pragma unroll
    for (int t = 0; t < 2; t++) {
        int rr = row0 + wm * 32 + t * 16 + (lane >> 2);
        #pragma unroll
        for (int j = 0; j < 8; j++) {
            int col = h * DD + wn * 64 + j * 8 + (lane & 3) * 2;
            #pragma unroll
            for (int half = 0; half < 2; half++) {
                float f0 = fin[t][j][half * 2 + 0], f1 = fin[t][j][half * 2 + 1];
                __nv_bfloat16 h0 = __float2bfloat16(f0), h1 = __float2bfloat16(f1);
                __nv_bfloat16 l0 = __float2bfloat16(f0 - __bfloat162float(h0));
                __nv_bfloat16 l1 = __float2bfloat16(f1 - __bfloat162float(h1));
                size_t off = (size_t)(rr + half * 8) * HIDC + col;
                *(__nv_bfloat162*)(cbh + off) = __nv_bfloat162(h0, h1);
                *(__nv_bfloat162*)(cbl + off) = __nv_bfloat162(l0, l1);
            }
        }
    }
}

// deltav + fused mem-update: 2 sub-tiles (256 rows) per block, bank0 copied once,
// P accumulated across sub-tiles -> g_part has 64 slices per head.
__global__ __launch_bounds__(256, 1) void deltav_hmma(
    const float* __restrict__ qkv,
    const __nv_bfloat16* __restrict__ mTh, const __nv_bfloat16* __restrict__ mTl,
    const __nv_bfloat16* __restrict__ nTh, const __nv_bfloat16* __restrict__ nTl,
    float* __restrict__ nsum, float* __restrict__ part)
{
    extern __shared__ char smem[];
    uint32_t sraw = smem_to_u32(smem);
    uint32_t sal = (sraw + 1023u) & ~1023u;
    char* sb = smem + (sal - sraw);
    int tid = threadIdx.x, lane = tid & 31, wid = tid >> 5;
    int wm = wid & 3, wn = wid >> 2;
    int h = blockIdx.y;
    int bx = blockIdx.x;            // 0..63

    copy_bank(mTh, mTl, 0, h, 0, sal, tid);
    if (tid < 128) {
        cp_async16(sal + CB_SNTH + tid * 16, nTh + h * 1024 + tid * 8);
        cp_async16(sal + CB_SNTL + tid * 16, nTl + h * 1024 + tid * 8);
    }
    cp_commit();

    float pac[2][8][4];
    #pragma unroll
    for (int t = 0; t < 2; t++)
        #pragma unroll
        for (int j = 0; j < 8; j++)
            #pragma unroll
            for (int p = 0; p < 4; p++) pac[t][j][p] = 0.f;

    const uint32_t DVB = CB_SB + 65536;   // dv hi/lo buffer (bank buf1 slot)

    for (int st = 0; st < 2; st++) {
        int row0 = bx * 256 + st * 128;
        if (st) __syncthreads();

        sigma_to_smem(qkv, row0, 2048 + h * DD, QKVW, sb, tid);   // k columns
        __syncthreads();
        if (st == 0) {
            asm volatile("cp.async.wait_group 0;" ::: "memory");
            __syncthreads();
        }
        if (wn == 0) norm_mma(sal, sb, wm, lane);

        {
            int col = tid & 127, hf = tid >> 7;
            float s = 0.f;
            for (int r = hf * 64; r < hf * 64 + 64; r++) {
                uint32_t off = (uint32_t)((col >> 6) * 16384) + SW128((uint32_t)(r * 128 + (col & 63) * 2));
                s += __bfloat162float(*(__nv_bfloat16*)(sb + CB_SAH + off))
                   + __bfloat162float(*(__nv_bfloat16*)(sb + CB_SAL + off));
            }
            ((float*)(sb + CB_SSUM))[hf * 128 + col] = s;
        }
        __syncthreads();

        float* sN = (float*)(sb + CB_SNORM);
        float* sC = (float*)(sb + CB_SCOEF);
        if (tid < 128) {
            sC[tid] = 1.f / fmaxf(sN[tid * 4], EPSF);
            float* ss = (float*)(sb + CB_SSUM);
            nsum[(size_t)(h * 128 + bx * 2 + st) * DD + tid] = ss[tid] + ss[128 + tid];
        }
        __syncthreads();

        float acc[2][8][4];
        #pragma unroll
        for (int t = 0; t < 2; t++)
            #pragma unroll
            for (int j = 0; j < 8; j++)
                #pragma unroll
                for (int p = 0; p < 4; p++) acc[t][j][p] = 0.f;
        bank_mma(sal, sal + CB_SB, wm, wn, lane, acc);

        #pragma unroll
        for (int t = 0; t < 2; t++) {
            int rloc = wm * 32 + t * 16 + (lane >> 2);
            float invA = sC[rloc], invB = sC[rloc + 8];
            int rr = row0 + rloc;
            #pragma unroll
            for (int j = 0; j < 8; j++) {
                int eloc = wn * 64 + j * 8 + (lane & 3) * 2;
                int col = 4096 + h * DD + eloc;
                float2 v0 = *(const float2*)&qkv[(size_t)rr * QKVW + col];
                float2 v1 = *(const float2*)&qkv[(size_t)(rr + 8) * QKVW + col];
                float d00 = v0.x - acc[t][j][0] * invA, d01 = v0.y - acc[t][j][1] * invA;
                float d10 = v1.x - acc[t][j][2] * invB, d11 = v1.y - acc[t][j][3] * invB;
                uint32_t off0 = ((uint32_t)(eloc >> 6) << 14) + SW128((uint32_t)(rloc * 128 + (eloc & 63) * 2));
                uint32_t off1 = ((uint32_t)(eloc >> 6) << 14) + SW128((uint32_t)((rloc + 8) * 128 + (eloc & 63) * 2));
                __nv_bfloat16 h00 = __float2bfloat16(d00), h01 = __float2bfloat16(d01);
                __nv_bfloat16 h10 = __float2bfloat16(d10), h11 = __float2bfloat16(d11);
                *(__nv_bfloat162*)(sb + DVB + off0) = __nv_bfloat162(h00, h01);
                *(__nv_bfloat162*)(sb + DVB + off1) = __nv_bfloat162(h10, h11);
                *(__nv_bfloat162*)(sb + DVB + 32768 + off0) =
                    __nv_bfloat162(__float2bfloat16(d00 - __bfloat162float(h00)),
                                   __float2bfloat16(d01 - __bfloat162float(h01)));
                *(__nv_bfloat162*)(sb + DVB + 32768 + off1) =
                    __nv_bfloat162(__float2bfloat16(d10 - __bfloat162float(h10)),
                                   __float2bfloat16(d11 - __bfloat162float(h11)));
            }
        }
        __syncthreads();

        #pragma unroll
        for (int ks = 0; ks < 8; ks++) {
            int rA = ks * 16 + (lane & 7) + ((lane >> 4) & 1) * 8;
            uint32_t ah[2][4], al[2][4];
            #pragma unroll
            for (int t = 0; t < 2; t++) {
                int dseg = wm * 32 + t * 16 + ((lane >> 3) & 1) * 8;
                uint32_t addr = sal + CB_SAH + ((uint32_t)(dseg >> 6) << 14) +
                    SW128((uint32_t)(rA * 128 + (dseg & 63) * 2));
                ldsm4t(ah[t], addr);
                ldsm4t(al[t], addr + 32768);
            }
            int rB = ks * 16 + (lane & 7) + ((lane >> 3) & 1) * 8;
            #pragma unroll
            for (int eg = 0; eg < 4; eg++) {
                int eseg = wn * 64 + eg * 16 + ((lane >> 4) & 1) * 8;
                uint32_t baddr = sal + DVB + ((uint32_t)(eseg >> 6) << 14) +
                    SW128((uint32_t)(rB * 128 + (eseg & 63) * 2));
                uint32_t bh[4], bl[4];
                ldsm4t(bh, baddr);
                ldsm4t(bl, baddr + 32768);
                #pragma unroll
                for (int t = 0; t < 2; t++) mma_bf16(pac[t][eg * 2 + 0], ah[t], bh);
                #pragma unroll
                for (int t = 0; t < 2; t++) mma_bf16(pac[t][eg * 2 + 1], ah[t], bh + 2);
                #pragma unroll
                for (int t = 0; t < 2; t++) mma_bf16(pac[t][eg * 2 + 0], ah[t], bl);
                #pragma unroll
                for (int t = 0; t < 2; t++) mma_bf16(pac[t][eg * 2 + 1], ah[t], bl + 2);
                #pragma unroll
                for (int t = 0; t < 2; t++) mma_bf16(pac[t][eg * 2 + 0], al[t], bh);
                #pragma unroll
                for (int t = 0; t < 2; t++) mma_bf16(pac[t][eg * 2 + 1], al[t], bh + 2);
            }
        }
    }

    size_t base = ((size_t)(h * 64 + bx)) << 14;
    #pragma unroll
    for (int t = 0; t < 2; t++) {
        int d0 = wm * 32 + t * 16 + (lane >> 2);
        #pragma unroll
        for (int j = 0; j < 8; j++) {
            int col = wn * 64 + j * 8 + (lane & 3) * 2;
            *(float2*)&part[base + (size_t)d0 * 128 + col]       = make_float2(pac[t][j][0], pac[t][j][1]);
            *(float2*)&part[base + (size_t)(d0 + 8) * 128 + col] = make_float2(pac[t][j][2], pac[t][j][3]);
        }
    }
}

// ===================== reductions =====================
__global__ void reduce_mem_kernel(const float* __restrict__ part,
                                  const float* __restrict__ memories,
                                  float* __restrict__ out)
{
    int t = blockIdx.x * blockDim.x + threadIdx.x;
    int h = t >> 14;
    int rem = t & 16383;
    float s = 0.f;
    #pragma unroll 8
    for (int sl = 0; sl < 64; sl++)
        s += part[((size_t)(h * 64 + sl) << 14) + rem];
    out[OUT_MEM + t] = memories[(size_t)h * DD * DD + rem] + s * (1.f / (float)BQ);
}

__global__ void reduce_norm_kernel(const float* __restrict__ nsum,
                                   const float* __restrict__ mnorms,
                                   float* __restrict__ out)
{
    int t = blockIdx.x * blockDim.x + threadIdx.x;
    int h = t >> 7, d = t & 127;
    float s = 0.f;
    for (int b = 0; b < 128; b++)
        s += nsum[(size_t)(h * 128 + b) * DD + d];
    out[OUT_NORM + t] = mnorms[(size_t)h * DD + d] + s * 0.25f;
}

// ---------------------------------------------------------------------------
extern "C" void kernel_launch(void* const* d_in, const int* in_sizes, int n_in,
                              void* d_out, int out_size)
{
    const float* hs = (const float*)d_in[0];
    const float* Wq = (const float*)d_in[1];
    const float* Wk = (const float*)d_in[2];
    const float* Wv = (const float*)d_in[3];
    const float* Wo = (const float*)d_in[4];
    const float* bw = (const float*)d_in[5];
    const float* mem = (const float*)d_in[6];
    const float* mnm = (const float*)d_in[7];
    float* out = (float*)d_out;

    float *pqkv, *ppart, *pnsum, *phsr, *pwr;
    __nv_bfloat16 *woh, *wol, *cbh, *cbl, *mTh, *mTl, *nTh, *nTl;
    cudaGetSymbolAddress((void**)&pqkv, g_qkv);
    cudaGetSymbolAddress((void**)&ppart, g_part);
    cudaGetSymbolAddress((void**)&pnsum, g_nsum);
    cudaGetSymbolAddress((void**)&phsr, g_hsr);
    cudaGetSymbolAddress((void**)&pwr, g_wr);
    cudaGetSymbolAddress((void**)&woh, g_wo_hi);
    cudaGetSymbolAddress((void**)&wol, g_wo_lo);
    cudaGetSymbolAddress((void**)&cbh, g_cb_hi);
    cudaGetSymbolAddress((void**)&cbl, g_cb_lo);
    cudaGetSymbolAddress((void**)&mTh, g_mTh);
    cudaGetSymbolAddress((void**)&mTl, g_mTl);
    cudaGetSymbolAddress((void**)&nTh, g_nTh);
    cudaGetSymbolAddress((void**)&nTl, g_nTl);

    static int smem_set = 0;
    if (!smem_set) {
        cudaFuncSetAttribute(tgemm32_kernel, cudaFuncAttributeMaxDynamicSharedMemorySize, T32_SMEM);
        cudaFuncSetAttribute(hgemm_kernel, cudaFuncAttributeMaxDynamicSharedMemorySize, HG_SMEM);
        cudaFuncSetAttribute(combined_hmma, cudaFuncAttributeMaxDynamicSharedMemorySize, CB_SMEM);
        cudaFuncSetAttribute(deltav_hmma, cudaFuncAttributeMaxDynamicSharedMemorySize, CB_SMEM);
        smem_set = 1;
    }

    const size_t WSZ = (size_t)HIDC * HIDC;

    prep_kernel<<<1, 128>>>(bw, mnm);                                          // 0
    cvt_round_kernel<<<(BQ * (size_t)HIDC) / 4 / 256, 256>>>(hs, phsr);        // 1
    cvt_round_kernel<<<WSZ / 4 / 256, 256>>>(Wq, pwr + 0 * WSZ);               // 2
    cvt_round_kernel<<<WSZ / 4 / 256, 256>>>(Wk, pwr + 1 * WSZ);               // 3
    cvt_round_kernel<<<WSZ / 4 / 256, 256>>>(Wv, pwr + 2 * WSZ);               // 4

    // fused QKV GEMM in single-pass tf32: N = 6144
    tgemm32_kernel<<<dim3(QKVW / 256, BQ / 128), 256, T32_SMEM>>>(phsr, pwr, pqkv, QKVW);  // 5

    cvt_split_kernel<<<WSZ / 4 / 256, 256>>>(Wo, woh, wol);
    prep2_kernel<<<NBANK * NH, 256>>>(mem, mTh, mTl);
    normt_kernel<<<NH, 256>>>(mnm, nTh, nTl);

    combined_hmma<<<dim3(BQ / 128, NH), 256, CB_SMEM>>>(pqkv, mTh, mTl, nTh, nTl, cbh, cbl);
    deltav_hmma<<<dim3(BQ / 256, NH), 256, CB_SMEM>>>(pqkv, mTh, mTl, nTh, nTl, pnsum, ppart);

    reduce_mem_kernel<<<(NH * DD * DD) / 256, 256>>>(ppart, mem, out);
    reduce_norm_kernel<<<(NH * DD) / 256, 256>>>(pnsum, mnm, out);

    hgemm_kernel<<<dim3(HIDC / 256, BQ / 128), 256, HG_SMEM>>>(cbh, cbl, woh, wol, out, HIDC);
}

// round 17
// speedup vs baseline: 1.0882x; 1.0285x over previous
#include <cuda_runtime.h>
#include <cuda_bf16.h>
#include <math.h>
#include <stdint.h>

// Problem constants
#define BQ   16384          // B*S rows
#define HIDC 2048
#define NH   16
#define DD   128
#define NBANK 4
#define EPSF 1e-6f
#define GK   2048
#define QKVW 6144           // fused qkv row width

#define OUT_MEM  ((size_t)BQ * HIDC)
#define OUT_NORM (OUT_MEM + (size_t)NH * DD * DD)

// -------- scratch (static device globals; no runtime allocation) ----------
__device__ float g_qkv[(size_t)BQ * QKVW];            // fused q|k|v projections
__device__ float g_part[(size_t)NH * 64 * DD * DD];   // mem-update partials (64 slices)
__device__ float g_nsum[(size_t)NH * 128 * DD];
__device__ float g_weff[NH][NBANK];

// tf32-rounded fp32 operands
__device__ float g_hsr[(size_t)BQ * HIDC];            // rounded hs, then rounded combined
__device__ float g_wr[(size_t)4 * HIDC * HIDC];       // Wq|Wk|Wv|Wo rounded

// pre-swizzled transposed memories (B-operand layout) + norm tiles
__device__ __nv_bfloat16 g_mTh[(size_t)NBANK * NH * DD * DD];
__device__ __nv_bfloat16 g_mTl[(size_t)NBANK * NH * DD * DD];
__device__ __nv_bfloat16 g_nTh[(size_t)NH * 1024];
__device__ __nv_bfloat16 g_nTl[(size_t)NH * 1024];

__device__ __forceinline__ float sigf(float x) { return x > 0.f ? x + 1.f : expf(x); }

__device__ __forceinline__ uint32_t smem_to_u32(const void* p) {
    uint32_t a;
    asm("{ .reg .u64 t; cvta.to.shared.u64 t, %1; cvt.u32.u64 %0, t; }" : "=r"(a) : "l"(p));
    return a;
}
#define SW128(off) ((off) ^ (((off) >> 3) & 0x70))

__device__ __forceinline__ void cp_async16(uint32_t saddr, const void* gaddr) {
    asm volatile("cp.async.cg.shared.global [%0], [%1], 16;" :: "r"(saddr), "l"(gaddr));
}
__device__ __forceinline__ void cp_commit() {
    asm volatile("cp.async.commit_group;" ::: "memory");
}
__device__ __forceinline__ void ldsm4(uint32_t* r, uint32_t addr) {
    asm volatile("ldmatrix.sync.aligned.m8n8.x4.shared.b16 {%0,%1,%2,%3}, [%4];"
        : "=r"(r[0]), "=r"(r[1]), "=r"(r[2]), "=r"(r[3]) : "r"(addr));
}
__device__ __forceinline__ void ldsm4t(uint32_t* r, uint32_t addr) {
    asm volatile("ldmatrix.sync.aligned.m8n8.x4.trans.shared.b16 {%0,%1,%2,%3}, [%4];"
        : "=r"(r[0]), "=r"(r[1]), "=r"(r[2]), "=r"(r[3]) : "r"(addr));
}
__device__ __forceinline__ void ldsm2(uint32_t* r, uint32_t addr) {
    asm volatile("ldmatrix.sync.aligned.m8n8.x2.shared.b16 {%0,%1}, [%2];"
        : "=r"(r[0]), "=r"(r[1]) : "r"(addr));
}
__device__ __forceinline__ void mma_bf16(float* c, const uint32_t* a, const uint32_t* b) {
    asm volatile("mma.sync.aligned.m16n8k16.row.col.f32.bf16.bf16.f32 "
        "{%0,%1,%2,%3}, {%4,%5,%6,%7}, {%8,%9}, {%0,%1,%2,%3};"
        : "+f"(c[0]), "+f"(c[1]), "+f"(c[2]), "+f"(c[3])
        : "r"(a[0]), "r"(a[1]), "r"(a[2]), "r"(a[3]), "r"(b[0]), "r"(b[1]));
}
__device__ __forceinline__ void mma_tf32(float* c, const uint32_t* a, const uint32_t* b) {
    asm volatile("mma.sync.aligned.m16n8k8.row.col.f32.tf32.tf32.f32 "
        "{%0,%1,%2,%3}, {%4,%5,%6,%7}, {%8,%9}, {%0,%1,%2,%3};"
        : "+f"(c[0]), "+f"(c[1]), "+f"(c[2]), "+f"(c[3])
        : "r"(a[0]), "r"(a[1]), "r"(a[2]), "r"(a[3]), "r"(b[0]), "r"(b[1]));
}
__device__ __forceinline__ uint32_t to_tf32(float x) {
    uint32_t r;
    asm("cvt.rna.tf32.f32 %0, %1;" : "=r"(r) : "f"(x));
    return r;
}

// ===================== tf32 rounding =====================
__global__ void cvt_round_kernel(const float* __restrict__ x, float* __restrict__ o)
{
    size_t i = ((size_t)blockIdx.x * blockDim.x + threadIdx.x) * 4;
    float4 v = *(const float4*)(x + i);
    uint4 r;
    r.x = to_tf32(v.x); r.y = to_tf32(v.y); r.z = to_tf32(v.z); r.w = to_tf32(v.w);
    *(uint4*)(o + i) = r;
}

// ===================== TF32 GEMM: C[M,N] = A[M,K] @ B[N,K]^T =====================
// fp32 (tf32-rounded) operands, single pass, ldmatrix fragment loads.
// Block 128m x 256n, warp 64x64, K-chunk 32, 3-stage cp.async.
// Padded smem stride 36 floats (144B, 16B-aligned, conflict-free for ldsm).
#define T32_STRIDE 36
#define T32_RB (T32_STRIDE * 4)                  // 144 bytes per row
#define T32_AS (128 * T32_RB)                    // 18432 B
#define T32_BS (256 * T32_RB)                    // 36864 B
#define T32_STG (T32_AS + T32_BS)                // 55296 B
#define T32_NCH 64                               // K / 32
#define T32_SMEM (3 * T32_STG + 1024)

__device__ __forceinline__ void t32_load_stage(
    const float* __restrict__ A, const float* __restrict__ B,
    uint32_t sb, int bm, int bn, int k0, int tid)
{
    #pragma unroll
    for (int it = 0; it < 4; it++) {
        int id = tid + it * 256;            // 0..1023 : A rows 0..127
        int r = id >> 3, c = id & 7;
        cp_async16(sb + (uint32_t)(r * T32_RB + c * 16),
                   A + (size_t)(bm + r) * GK + k0 + c * 4);
    }
    #pragma unroll
    for (int it = 0; it < 8; it++) {
        int id = tid + it * 256;            // 0..2047 : B rows 0..255
        int r = id >> 3, c = id & 7;
        cp_async16(sb + T32_AS + (uint32_t)(r * T32_RB + c * 16),
                   B + (size_t)(bn + r) * GK + k0 + c * 4);
    }
}

__global__ __launch_bounds__(256, 1)
void tgemm32_kernel(const float* __restrict__ A, const float* __restrict__ B,
                    float* __restrict__ C, int N)
{
    extern __shared__ char smem[];
    uint32_t sraw = smem_to_u32(smem);
    uint32_t sal = (sraw + 1023u) & ~1023u;

    int tid = threadIdx.x;
    int lane = tid & 31, wid = tid >> 5;
    int wm = wid >> 2, wn = wid & 3;        // warp tile 64m x 64n
    int bm = blockIdx.y * 128;
    int bn = blockIdx.x * 256;
    int grp = lane >> 2, tig = lane & 3;

    float acc[4][8][4];
    #pragma unroll
    for (int t = 0; t < 4; t++)
        #pragma unroll
        for (int n = 0; n < 8; n++)
            #pragma unroll
            for (int j = 0; j < 4; j++) acc[t][n][j] = 0.f;

    t32_load_stage(A, B, sal, bm, bn, 0, tid);
    cp_commit();
    t32_load_stage(A, B, sal + T32_STG, bm, bn, 32, tid);
    cp_commit();

    // ldsm lane offsets (bytes, relative to tile base)
    // A x4: m0 rows0-7/c0-3, m1 rows8-15/c0-3, m2 rows0-7/c4-7, m3 rows8-15/c4-7
    uint32_t a_lane = (uint32_t)(((lane & 7) + ((lane >> 3) & 1) * 8) * T32_RB + (lane >> 4) * 16);
    // B x4: m0 n0-7/k0-3 (b0 even), m1 n0-7/k4-7 (b1 even), m2 n8-15/k0-3, m3 n8-15/k4-7
    uint32_t b_lane = (uint32_t)(((lane & 7) + (lane >> 4) * 8) * T32_RB + ((lane >> 3) & 1) * 16);

    for (int c = 0; c < T32_NCH; c++) {
        if (c == T32_NCH - 1) { asm volatile("cp.async.wait_group 0;" ::: "memory"); }
        else                  { asm volatile("cp.async.wait_group 1;" ::: "memory"); }
        __syncthreads();
        uint32_t sA = sal + (c % 3) * T32_STG;
        uint32_t sB = sA + T32_AS;

        #pragma unroll
        for (int ks = 0; ks < 4; ks++) {
            uint32_t af[4][4];
            #pragma unroll
            for (int t = 0; t < 4; t++)
                ldsm4(af[t], sA + (uint32_t)((wm * 64 + t * 16) * T32_RB) + a_lane + ks * 32);
            #pragma unroll
            for (int p = 0; p < 4; p++) {
                uint32_t bf[4];
                ldsm4(bf, sB + (uint32_t)((wn * 64 + p * 16) * T32_RB) + b_lane + ks * 32);
                #pragma unroll
                for (int t = 0; t < 4; t++) mma_tf32(acc[t][p * 2 + 0], af[t], bf);
                #pragma unroll
                for (int t = 0; t < 4; t++) mma_tf32(acc[t][p * 2 + 1], af[t], bf + 2);
            }
        }
        __syncthreads();
        if (c + 2 < T32_NCH) {
            t32_load_stage(A, B, sal + ((c + 2) % 3) * T32_STG, bm, bn, (c + 2) * 32, tid);
            cp_commit();
        }
    }

    #pragma unroll
    for (int t = 0; t < 4; t++) {
        int r0 = bm + wm * 64 + t * 16 + grp;
        #pragma unroll
        for (int ng = 0; ng < 8; ng++) {
            int col = bn + wn * 64 + ng * 8 + tig * 2;
            *(float2*)&C[(size_t)r0 * N + col]       = make_float2(acc[t][ng][0], acc[t][ng][1]);
            *(float2*)&C[(size_t)(r0 + 8) * N + col] = make_float2(acc[t][ng][2], acc[t][ng][3]);
        }
    }
}

// ===================== K0: softmax of bank weights + active flags =====================
__global__ void prep_kernel(const float* __restrict__ bw, const float* __restrict__ mn) {
    __shared__ float bsum[NBANK];
    int tid = threadIdx.x;
    int w = tid >> 5, lane = tid & 31;
    if (w < NBANK) {
        float s = 0.f;
        for (int i = lane; i < NH * DD; i += 32) s += mn[w * NH * DD + i];
        #pragma unroll
        for (int o = 16; o; o >>= 1) s += __shfl_down_sync(0xffffffffu, s, o);
        if (lane == 0) bsum[w] = s;
    }
    __syncthreads();
    if (tid < NH) {
        float x0 = bw[tid * 4 + 0], x1 = bw[tid * 4 + 1];
        float x2 = bw[tid * 4 + 2], x3 = bw[tid * 4 + 3];
        float m = fmaxf(fmaxf(x0, x1), fmaxf(x2, x3));
        float e0 = expf(x0 - m), e1 = expf(x1 - m), e2 = expf(x2 - m), e3 = expf(x3 - m);
        float inv = 1.f / (e0 + e1 + e2 + e3);
        g_weff[tid][0] = e0 * inv * (bsum[0] >= EPSF ? 1.f : 0.f);
        g_weff[tid][1] = e1 * inv * (bsum[1] >= EPSF ? 1.f : 0.f);
        g_weff[tid][2] = e2 * inv * (bsum[2] >= EPSF ? 1.f : 0.f);
        g_weff[tid][3] = e3 * inv * (bsum[3] >= EPSF ? 1.f : 0.f);
    }
}

// ===================== prep2: memories -> transposed, split, pre-swizzled =====================
__global__ void prep2_kernel(const float* __restrict__ mem,
                             __nv_bfloat16* __restrict__ mTh, __nv_bfloat16* __restrict__ mTl)
{
    int nh = blockIdx.x;     // 0..63
    const float* src = mem + (size_t)nh * 16384;
    __nv_bfloat16* dh = mTh + (size_t)nh * 16384;
    __nv_bfloat16* dl = mTl + (size_t)nh * 16384;
    for (int i = threadIdx.x; i < 16384; i += 256) {
        int d = i >> 7, e = i & 127;
        float v = src[d * 128 + e];
        __nv_bfloat16 hi = __float2bfloat16(v);
        __nv_bfloat16 lo = __float2bfloat16(v - __bfloat162float(hi));
        uint32_t off = ((uint32_t)(d >> 6) << 13) +
                       (SW128((uint32_t)(e * 128 + (d & 63) * 2)) >> 1);
        dh[off] = hi; dl[off] = lo;
    }
}

__global__ void normt_kernel(const float* __restrict__ mnm,
                             __nv_bfloat16* __restrict__ nTh, __nv_bfloat16* __restrict__ nTl)
{
    int h = blockIdx.x;
    for (int i = threadIdx.x; i < 1024; i += 256) {
        int nr = i >> 7, d = i & 127;
        float v = (nr < NBANK) ? mnm[(size_t)(nr * NH + h) * DD + d] : 0.f;
        __nv_bfloat16 hi = __float2bfloat16(v);
        __nv_bfloat16 lo = __float2bfloat16(v - __bfloat162float(hi));
        uint32_t off = ((uint32_t)(d >> 6) << 9) +
                       (SW128((uint32_t)(nr * 128 + (d & 63) * 2)) >> 1);
        nTh[h * 1024 + off] = hi; nTl[h * 1024 + off] = lo;
    }
}

// ===================== HMMA combined / deltav =====================
#define CB_SAH   0
#define CB_SAL   32768
#define CB_SB    65536
#define CB_SNTH  196608
#define CB_SNTL  198656
#define CB_SNORM 200704
#define CB_SCOEF 202752
#define CB_SSUM  204800
#define CB_SMEM  207872

__device__ __forceinline__ void sigma_to_smem(const float* __restrict__ src, int row0,
                                              int colbase, int stride, char* sb, int tid)
{
    #pragma unroll
    for (int i = 0; i < 16; i++) {
        int id = tid + i * 256;
        int r = id >> 5, c4 = id & 31;
        float4 v = *(const float4*)&src[(size_t)(row0 + r) * stride + colbase + c4 * 4];
        float s0 = sigf(v.x), s1 = sigf(v.y), s2 = sigf(v.z), s3 = sigf(v.w);
        __nv_bfloat16 h0 = __float2bfloat16(s0), h1 = __float2bfloat16(s1);
        __nv_bfloat16 h2 = __float2bfloat16(s2), h3 = __float2bfloat16(s3);
        __nv_bfloat16 l0 = __float2bfloat16(s0 - __bfloat162float(h0));
        __nv_bfloat16 l1 = __float2bfloat16(s1 - __bfloat162float(h1));
        __nv_bfloat16 l2 = __float2bfloat16(s2 - __bfloat162float(h2));
        __nv_bfloat16 l3 = __float2bfloat16(s3 - __bfloat162float(h3));
        int d0 = c4 * 4;
        uint32_t off = (uint32_t)((d0 >> 6) * 16384) + SW128((uint32_t)(r * 128 + (d0 & 63) * 2));
        *(__nv_bfloat162*)(sb + CB_SAH + off)     = __nv_bfloat162(h0, h1);
        *(__nv_bfloat162*)(sb + CB_SAH + off + 4) = __nv_bfloat162(h2, h3);
        *(__nv_bfloat162*)(sb + CB_SAL + off)     = __nv_bfloat162(l0, l1);
        *(__nv_bfloat162*)(sb + CB_SAL + off + 4) = __nv_bfloat162(l2, l3);
    }
}

__device__ __forceinline__ void norm_mma(uint32_t sal, char* sb, int wm, int lane)
{
    float nc[2][4];
    #pragma unroll
    for (int t = 0; t < 2; t++)
        #pragma unroll
        for (int j = 0; j < 4; j++) nc[t][j] = 0.f;
    #pragma unroll
    for (int ks = 0; ks < 8; ks++) {
        uint32_t ah[2][4], al[2][4];
        #pragma unroll
        for (int t = 0; t < 2; t++) {
            uint32_t aaddr = sal + CB_SAH + (ks >> 2) * 16384 +
                SW128((uint32_t)((wm * 32 + t * 16 + (lane & 15)) * 128 + (ks & 3) * 32 + (lane >> 4) * 16));
            ldsm4(ah[t], aaddr);
            ldsm4(al[t], aaddr + 32768);
        }
        uint32_t bh[2], bl[2];
        uint32_t naddr = sal + CB_SNTH + (ks >> 2) * 1024 +
            SW128((uint32_t)((lane & 7) * 128 + (ks & 3) * 32 + ((lane >> 3) & 1) * 16));
        ldsm2(bh, naddr);
        ldsm2(bl, naddr + 2048);
        #pragma unroll
        for (int t = 0; t < 2; t++) mma_bf16(nc[t], ah[t], bh);
        #pragma unroll
        for (int t = 0; t < 2; t++) mma_bf16(nc[t], al[t], bh);
        #pragma unroll
        for (int t = 0; t < 2; t++) mma_bf16(nc[t], ah[t], bl);
    }
    float* sN = (float*)(sb + CB_SNORM);
    if ((lane & 3) < 2) {
        #pragma unroll
        for (int t = 0; t < 2; t++) {
            int rr = wm * 32 + t * 16 + (lane >> 2);
            sN[rr * 4 + (lane & 3) * 2]           = nc[t][0];
            sN[rr * 4 + (lane & 3) * 2 + 1]       = nc[t][1];
            sN[(rr + 8) * 4 + (lane & 3) * 2]     = nc[t][2];
            sN[(rr + 8) * 4 + (lane & 3) * 2 + 1] = nc[t][3];
        }
    }
}

__device__ __forceinline__ void bank_mma(uint32_t sal, uint32_t sbB, int wm, int wn, int lane,
                                         float acc[2][8][4])
{
    #pragma unroll
    for (int ks = 0; ks < 8; ks++) {
        uint32_t ah[2][4], al[2][4];
        #pragma unroll
        for (int t = 0; t < 2; t++) {
            uint32_t aaddr = sal + CB_SAH + (ks >> 2) * 16384 +
                SW128((uint32_t)((wm * 32 + t * 16 + (lane & 15)) * 128 + (ks & 3) * 32 + (lane >> 4) * 16));
            ldsm4(ah[t], aaddr);
            ldsm4(al[t], aaddr + 32768);
        }
        #pragma unroll
        for (int nt = 0; nt < 4; nt++) {
            uint32_t baddr = sbB + (ks >> 2) * 16384 +
                SW128((uint32_t)((wn * 64 + nt * 16 + ((lane >> 4) << 3) + (lane & 7)) * 128 +
                                 (ks & 3) * 32 + ((lane >> 3) & 1) * 16));
            uint32_t bh[4], bl[4];
            ldsm4(bh, baddr);
            ldsm4(bl, baddr + 32768);
            #pragma unroll
            for (int t = 0; t < 2; t++) mma_bf16(acc[t][nt * 2 + 0], ah[t], bh);
            #pragma unroll
            for (int t = 0; t < 2; t++) mma_bf16(acc[t][nt * 2 + 1], ah[t], bh + 2);
            #pragma unroll
            for (int t = 0; t < 2; t++) mma_bf16(acc[t][nt * 2 + 0], ah[t], bl);
            #pragma unroll
            for (int t = 0; t < 2; t++) mma_bf16(acc[t][nt * 2 + 1], ah[t], bl + 2);
            #pragma unroll
            for (int t = 0; t < 2; t++) mma_bf16(acc[t][nt * 2 + 0], al[t], bh);
            #pragma unroll
            for (int t = 0; t < 2; t++) mma_bf16(acc[t][nt * 2 + 1], al[t], bh + 2);
        }
    }
}

__device__ __forceinline__ void copy_bank(const __nv_bfloat16* mTh, const __nv_bfloat16* mTl,
                                          int n, int h, int buf, uint32_t sal, int tid)
{
    const __nv_bfloat16* sh = mTh + ((size_t)(n * NH + h) << 14);
    const __nv_bfloat16* sl = mTl + ((size_t)(n * NH + h) << 14);
    uint32_t dst = sal + CB_SB + buf * 65536;
    #pragma unroll
    for (int i = 0; i < 8; i++) {
        int id = tid + i * 256;
        cp_async16(dst + id * 16, sh + id * 8);
        cp_async16(dst + 32768 + id * 16, sl + id * 8);
    }
}

__global__ __launch_bounds__(256, 1) void combined_hmma(
    const float* __restrict__ qkv,
    const __nv_bfloat16* __restrict__ mTh, const __nv_bfloat16* __restrict__ mTl,
    const __nv_bfloat16* __restrict__ nTh, const __nv_bfloat16* __restrict__ nTl,
    float* __restrict__ cbr)
{
    extern __shared__ char smem[];
    uint32_t sraw = smem_to_u32(smem);
    uint32_t sal = (sraw + 1023u) & ~1023u;
    char* sb = smem + (sal - sraw);
    int tid = threadIdx.x, lane = tid & 31, wid = tid >> 5;
    int wm = wid & 3, wn = wid >> 2;
    int h = blockIdx.y;
    int row0 = blockIdx.x * 128;

    copy_bank(mTh, mTl, 0, h, 0, sal, tid);
    if (tid < 128) {
        cp_async16(sal + CB_SNTH + tid * 16, nTh + h * 1024 + tid * 8);
        cp_async16(sal + CB_SNTL + tid * 16, nTl + h * 1024 + tid * 8);
    }
    cp_commit();
    copy_bank(mTh, mTl, 1, h, 1, sal, tid);
    cp_commit();

    sigma_to_smem(qkv, row0, h * DD, QKVW, sb, tid);   // q columns
    __syncthreads();

    asm volatile("cp.async.wait_group 1;" ::: "memory");
    __syncthreads();
    if (wn == 0) norm_mma(sal, sb, wm, lane);
    __syncthreads();

    float* sN = (float*)(sb + CB_SNORM);
    float* sC = (float*)(sb + CB_SCOEF);
    {
        int rr = tid >> 1, base = (tid & 1) * 2;
        sC[rr * 4 + base]     = g_weff[h][base]     / fmaxf(sN[rr * 4 + base], EPSF);
        sC[rr * 4 + base + 1] = g_weff[h][base + 1] / fmaxf(sN[rr * 4 + base + 1], EPSF);
    }
    __syncthreads();

    float fin[2][8][4];
    #pragma unroll
    for (int t = 0; t < 2; t++)
        #pragma unroll
        for (int j = 0; j < 8; j++)
            #pragma unroll
            for (int p = 0; p < 4; p++) fin[t][j][p] = 0.f;

    for (int n = 0; n < NBANK; n++) {
        if (n < 3) { asm volatile("cp.async.wait_group 1;" ::: "memory"); }
        else       { asm volatile("cp.async.wait_group 0;" ::: "memory"); }
        __syncthreads();
        float acc[2][8][4];
        #pragma unroll
        for (int t = 0; t < 2; t++)
            #pragma unroll
            for (int j = 0; j < 8; j++)
                #pragma unroll
                for (int p = 0; p < 4; p++) acc[t][j][p] = 0.f;
        bank_mma(sal, sal + CB_SB + (n & 1) * 65536, wm, wn, lane, acc);
        __syncthreads();
        if (n + 2 < NBANK) { copy_bank(mTh, mTl, n + 2, h, n & 1, sal, tid); cp_commit(); }
        #pragma unroll
        for (int t = 0; t < 2; t++) {
            int rrA = wm * 32 + t * 16 + (lane >> 2);
            float cA = sC[rrA * 4 + n], cB = sC[(rrA + 8) * 4 + n];
            #pragma unroll
            for (int j = 0; j < 8; j++) {
                fin[t][j][0] += cA * acc[t][j][0];
                fin[t][j][1] += cA * acc[t][j][1];
                fin[t][j][2] += cB * acc[t][j][2];
                fin[t][j][3] += cB * acc[t][j][3];
            }
        }
    }

    // write combined directly as tf32-rounded fp32 (operand of output tf32 GEMM)
    #pragma unroll
    for (int t = 0; t < 2; t++) {
        int rr = row0 + wm * 32 + t * 16 + (lane >> 2);
        #pragma unroll
        for (int j = 0; j < 8; j++) {
            int col = h * DD + wn * 64 + j * 8 + (lane & 3) * 2;
            *(float2*)&cbr[(size_t)rr * HIDC + col] =
                make_float2(__uint_as_float(to_tf32(fin[t][j][0])),
                            __uint_as_float(to_tf32(fin[t][j][1])));
            *(float2*)&cbr[(size_t)(rr + 8) * HIDC + col] =
                make_float2(__uint_as_float(to_tf32(fin[t][j][2])),
                            __uint_as_float(to_tf32(fin[t][j][3])));
        }
    }
}

// deltav + fused mem-update: 2 sub-tiles (256 rows) per block, bank0 copied once,
// P accumulated across sub-tiles -> g_part has 64 slices per head.
__global__ __launch_bounds__(256, 1) void deltav_hmma(
    const float* __restrict__ qkv,
    const __nv_bfloat16* __restrict__ mTh, const __nv_bfloat16* __restrict__ mTl,
    const __nv_bfloat16* __restrict__ nTh, const __nv_bfloat16* __restrict__ nTl,
    float* __restrict__ nsum, float* __restrict__ part)
{
    extern __shared__ char smem[];
    uint32_t sraw = smem_to_u32(smem);
    uint32_t sal = (sraw + 1023u) & ~1023u;
    char* sb = smem + (sal - sraw);
    int tid = threadIdx.x, lane = tid & 31, wid = tid >> 5;
    int wm = wid & 3, wn = wid >> 2;
    int h = blockIdx.y;
    int bx = blockIdx.x;            // 0..63

    copy_bank(mTh, mTl, 0, h, 0, sal, tid);
    if (tid < 128) {
        cp_async16(sal + CB_SNTH + tid * 16, nTh + h * 1024 + tid * 8);
        cp_async16(sal + CB_SNTL + tid * 16, nTl + h * 1024 + tid * 8);
    }
    cp_commit();

    float pac[2][8][4];
    #pragma unroll
    for (int t = 0; t < 2; t++)
        #pragma unroll
        for (int j = 0; j < 8; j++)
            #pragma unroll
            for (int p = 0; p < 4; p++) pac[t][j][p] = 0.f;

    const uint32_t DVB = CB_SB + 65536;   // dv hi/lo buffer (bank buf1 slot)

    for (int st = 0; st < 2; st++) {
        int row0 = bx * 256 + st * 128;
        if (st) __syncthreads();

        sigma_to_smem(qkv, row0, 2048 + h * DD, QKVW, sb, tid);   // k columns
        __syncthreads();
        if (st == 0) {
            asm volatile("cp.async.wait_group 0;" ::: "memory");
            __syncthreads();
        }
        if (wn == 0) norm_mma(sal, sb, wm, lane);

        {
            int col = tid & 127, hf = tid >> 7;
            float s = 0.f;
            for (int r = hf * 64; r < hf * 64 + 64; r++) {
                uint32_t off = (uint32_t)((col >> 6) * 16384) + SW128((uint32_t)(r * 128 + (col & 63) * 2));
                s += __bfloat162float(*(__nv_bfloat16*)(sb + CB_SAH + off))
                   + __bfloat162float(*(__nv_bfloat16*)(sb + CB_SAL + off));
            }
            ((float*)(sb + CB_SSUM))[hf * 128 + col] = s;
        }
        __syncthreads();

        float* sN = (float*)(sb + CB_SNORM);
        float* sC = (float*)(sb + CB_SCOEF);
        if (tid < 128) {
            sC[tid] = 1.f / fmaxf(sN[tid * 4], EPSF);
            float* ss = (float*)(sb + CB_SSUM);
            nsum[(size_t)(h * 128 + bx * 2 + st) * DD + tid] = ss[tid] + ss[128 + tid];
        }
        __syncthreads();

        float acc[2][8][4];
        #pragma unroll
        for (int t = 0; t < 2; t++)
            #pragma unroll
            for (int j = 0; j < 8; j++)
                #pragma unroll
                for (int p = 0; p < 4; p++) acc[t][j][p] = 0.f;
        bank_mma(sal, sal + CB_SB, wm, wn, lane, acc);

        #pragma unroll
        for (int t = 0; t < 2; t++) {
            int rloc = wm * 32 + t * 16 + (lane >> 2);
            float invA = sC[rloc], invB = sC[rloc + 8];
            int rr = row0 + rloc;
            #pragma unroll
            for (int j = 0; j < 8; j++) {
                int eloc = wn * 64 + j * 8 + (lane & 3) * 2;
                int col = 4096 + h * DD + eloc;
                float2 v0 = *(const float2*)&qkv[(size_t)rr * QKVW + col];
                float2 v1 = *(const float2*)&qkv[(size_t)(rr + 8) * QKVW + col];
                float d00 = v0.x - acc[t][j][0] * invA, d01 = v0.y - acc[t][j][1] * invA;
                float d10 = v1.x - acc[t][j][2] * invB, d11 = v1.y - acc[t][j][3] * invB;
                uint32_t off0 = ((uint32_t)(eloc >> 6) << 14) + SW128((uint32_t)(rloc * 128 + (eloc & 63) * 2));
                uint32_t off1 = ((uint32_t)(eloc >> 6) << 14) + SW128((uint32_t)((rloc + 8) * 128 + (eloc & 63) * 2));
                __nv_bfloat16 h00 = __float2bfloat16(d00), h01 = __float2bfloat16(d01);
                __nv_bfloat16 h10 = __float2bfloat16(d10), h11 = __float2bfloat16(d11);
                *(__nv_bfloat162*)(sb + DVB + off0) = __nv_bfloat162(h00, h01);
                *(__nv_bfloat162*)(sb + DVB + off1) = __nv_bfloat162(h10, h11);
                *(__nv_bfloat162*)(sb + DVB + 32768 + off0) =
                    __nv_bfloat162(__float2bfloat16(d00 - __bfloat162float(h00)),
                                   __float2bfloat16(d01 - __bfloat162float(h01)));
                *(__nv_bfloat162*)(sb + DVB + 32768 + off1) =
                    __nv_bfloat162(__float2bfloat16(d10 - __bfloat162float(h10)),
                                   __float2bfloat16(d11 - __bfloat162float(h11)));
            }
        }
        __syncthreads();

        #pragma unroll
        for (int ks = 0; ks < 8; ks++) {
            int rA = ks * 16 + (lane & 7) + ((lane >> 4) & 1) * 8;
            uint32_t ah[2][4], al[2][4];
            #pragma unroll
            for (int t = 0; t < 2; t++) {
                int dseg = wm * 32 + t * 16 + ((lane >> 3) & 1) * 8;
                uint32_t addr = sal + CB_SAH + ((uint32_t)(dseg >> 6) << 14) +
                    SW128((uint32_t)(rA * 128 + (dseg & 63) * 2));
                ldsm4t(ah[t], addr);
                ldsm4t(al[t], addr + 32768);
            }
            int rB = ks * 16 + (lane & 7) + ((lane >> 3) & 1) * 8;
            #pragma unroll
            for (int eg = 0; eg < 4; eg++) {
                int eseg = wn * 64 + eg * 16 + ((lane >> 4) & 1) * 8;
                uint32_t baddr = sal + DVB + ((uint32_t)(eseg >> 6) << 14) +
                    SW128((uint32_t)(rB * 128 + (eseg & 63) * 2));
                uint32_t bh[4], bl[4];
                ldsm4t(bh, baddr);
                ldsm4t(bl, baddr + 32768);
                #pragma unroll
                for (int t = 0; t < 2; t++) mma_bf16(pac[t][eg * 2 + 0], ah[t], bh);
                #pragma unroll
                for (int t = 0; t < 2; t++) mma_bf16(pac[t][eg * 2 + 1], ah[t], bh + 2);
                #pragma unroll
                for (int t = 0; t < 2; t++) mma_bf16(pac[t][eg * 2 + 0], ah[t], bl);
                #pragma unroll
                for (int t = 0; t < 2; t++) mma_bf16(pac[t][eg * 2 + 1], ah[t], bl + 2);
                #pragma unroll
                for (int t = 0; t < 2; t++) mma_bf16(pac[t][eg * 2 + 0], al[t], bh);
                #pragma unroll
                for (int t = 0; t < 2; t++) mma_bf16(pac[t][eg * 2 + 1], al[t], bh + 2);
            }
        }
    }

    size_t base = ((size_t)(h * 64 + bx)) << 14;
    #pragma unroll
    for (int t = 0; t < 2; t++) {
        int d0 = wm * 32 + t * 16 + (lane >> 2);
        #pragma unroll
        for (int j = 0; j < 8; j++) {
            int col = wn * 64 + j * 8 + (lane & 3) * 2;
            *(float2*)&part[base + (size_t)d0 * 128 + col]       = make_float2(pac[t][j][0], pac[t][j][1]);
            *(float2*)&part[base + (size_t)(d0 + 8) * 128 + col] = make_float2(pac[t][j][2], pac[t][j][3]);
        }
    }
}

// ===================== reductions =====================
__global__ void reduce_mem_kernel(const float* __restrict__ part,
                                  const float* __restrict__ memories,
                                  float* __restrict__ out)
{
    int t = blockIdx.x * blockDim.x + threadIdx.x;
    int h = t >> 14;
    int rem = t & 16383;
    float s = 0.f;
    #pragma unroll 8
    for (int sl = 0; sl < 64; sl++)
        s += part[((size_t)(h * 64 + sl) << 14) + rem];
    out[OUT_MEM + t] = memories[(size_t)h * DD * DD + rem] + s * (1.f / (float)BQ);
}

__global__ void reduce_norm_kernel(const float* __restrict__ nsum,
                                   const float* __restrict__ mnorms,
                                   float* __restrict__ out)
{
    int t = blockIdx.x * blockDim.x + threadIdx.x;
    int h = t >> 7, d = t & 127;
    float s = 0.f;
    for (int b = 0; b < 128; b++)
        s += nsum[(size_t)(h * 128 + b) * DD + d];
    out[OUT_NORM + t] = mnorms[(size_t)h * DD + d] + s * 0.25f;
}

// ---------------------------------------------------------------------------
extern "C" void kernel_launch(void* const* d_in, const int* in_sizes, int n_in,
                              void* d_out, int out_size)
{
    const float* hs = (const float*)d_in[0];
    const float* Wq = (const float*)d_in[1];
    const float* Wk = (const float*)d_in[2];
    const float* Wv = (const float*)d_in[3];
    const float* Wo = (const float*)d_in[4];
    const float* bw = (const float*)d_in[5];
    const float* mem = (const float*)d_in[6];
    const float* mnm = (const float*)d_in[7];
    float* out = (float*)d_out;

    float *pqkv, *ppart, *pnsum, *phsr, *pwr;
    __nv_bfloat16 *mTh, *mTl, *nTh, *nTl;
    cudaGetSymbolAddress((void**)&pqkv, g_qkv);
    cudaGetSymbolAddress((void**)&ppart, g_part);
    cudaGetSymbolAddress((void**)&pnsum, g_nsum);
    cudaGetSymbolAddress((void**)&phsr, g_hsr);
    cudaGetSymbolAddress((void**)&pwr, g_wr);
    cudaGetSymbolAddress((void**)&mTh, g_mTh);
    cudaGetSymbolAddress((void**)&mTl, g_mTl);
    cudaGetSymbolAddress((void**)&nTh, g_nTh);
    cudaGetSymbolAddress((void**)&nTl, g_nTl);

    static int smem_set = 0;
    if (!smem_set) {
        cudaFuncSetAttribute(tgemm32_kernel, cudaFuncAttributeMaxDynamicSharedMemorySize, T32_SMEM);
        cudaFuncSetAttribute(combined_hmma, cudaFuncAttributeMaxDynamicSharedMemorySize, CB_SMEM);
        cudaFuncSetAttribute(deltav_hmma, cudaFuncAttributeMaxDynamicSharedMemorySize, CB_SMEM);
        smem_set = 1;
    }

    const size_t WSZ = (size_t)HIDC * HIDC;

    prep_kernel<<<1, 128>>>(bw, mnm);                                          // 0
    cvt_round_kernel<<<(BQ * (size_t)HIDC) / 4 / 256, 256>>>(hs, phsr);        // 1
    cvt_round_kernel<<<WSZ / 4 / 256, 256>>>(Wq, pwr + 0 * WSZ);               // 2
    cvt_round_kernel<<<WSZ / 4 / 256, 256>>>(Wk, pwr + 1 * WSZ);               // 3
    cvt_round_kernel<<<WSZ / 4 / 256, 256>>>(Wv, pwr + 2 * WSZ);               // 4

    // fused QKV GEMM in single-pass tf32 (ldmatrix fragments): N = 6144
    tgemm32_kernel<<<dim3(QKVW / 256, BQ / 128), 256, T32_SMEM>>>(phsr, pwr, pqkv, QKVW);  // 5

    cvt_round_kernel<<<WSZ / 4 / 256, 256>>>(Wo, pwr + 3 * WSZ);
    prep2_kernel<<<NBANK * NH, 256>>>(mem, mTh, mTl);
    normt_kernel<<<NH, 256>>>(mnm, nTh, nTl);

    // combined writes tf32-rounded fp32 into phsr (hs-rounded no longer needed)
    combined_hmma<<<dim3(BQ / 128, NH), 256, CB_SMEM>>>(pqkv, mTh, mTl, nTh, nTl, phsr);
    deltav_hmma<<<dim3(BQ / 256, NH), 256, CB_SMEM>>>(pqkv, mTh, mTl, nTh, nTl, pnsum, ppart);

    reduce_mem_kernel<<<(NH * DD * DD) / 256, 256>>>(ppart, mem, out);
    reduce_norm_kernel<<<(NH * DD) / 256, 256>>>(pnsum, mnm, out);

    // output GEMM in tf32
    tgemm32_kernel<<<dim3(HIDC / 256, BQ / 128), 256, T32_SMEM>>>(phsr, pwr + 3 * WSZ, out, HIDC);
}